// round 1
// baseline (speedup 1.0000x reference)
#include <cuda_runtime.h>
#include <cuda_bf16.h>
#include <math.h>

// ---------------------------------------------------------------------------
// Problem constants
// ---------------------------------------------------------------------------
#define BATCH    2
#define SEQ      2048
#define DIM      1024
#define NHEAD    16
#define HDIM     64
#define HIDDEN   4096
#define TOKENS   (BATCH * SEQ)          // 4096
#define QKV_DIM  (3 * DIM)              // 3072
#define LN_EPS   1e-5f

// ---------------------------------------------------------------------------
// Scratch buffers (static __device__ — allocation inside kernel_launch is
// forbidden by the harness rules)
// ---------------------------------------------------------------------------
__device__ float g_xn [TOKENS * DIM];      // layernorm output (reused for ln1/ln2)
__device__ float g_qkv[TOKENS * QKV_DIM];  // qkv projection
__device__ float g_att[TOKENS * DIM];      // attention output (pre-proj)
__device__ float g_x1 [TOKENS * DIM];      // x + attn residual
__device__ float g_h  [TOKENS * HIDDEN];   // ff1 output (post-GELU)

// ---------------------------------------------------------------------------
// LayerNorm: one block per row (1024 cols), 256 threads, float4 loads
// ---------------------------------------------------------------------------
__global__ void ln_kernel(const float* __restrict__ in,
                          const float* __restrict__ gamma,
                          const float* __restrict__ beta,
                          float* __restrict__ out)
{
    int row = blockIdx.x;
    int tid = threadIdx.x;               // 256
    const float4* rp = (const float4*)(in + (size_t)row * DIM);
    float4 v = rp[tid];

    float s  = v.x + v.y + v.z + v.w;
    float s2 = v.x*v.x + v.y*v.y + v.z*v.z + v.w*v.w;

    __shared__ float rs[256];
    __shared__ float rq[256];
    rs[tid] = s; rq[tid] = s2;
    __syncthreads();
    #pragma unroll
    for (int o = 128; o > 0; o >>= 1) {
        if (tid < o) { rs[tid] += rs[tid + o]; rq[tid] += rq[tid + o]; }
        __syncthreads();
    }
    float mu  = rs[0] * (1.0f / DIM);
    float var = rq[0] * (1.0f / DIM) - mu * mu;
    float rstd = rsqrtf(var + LN_EPS);

    float4 g4 = ((const float4*)gamma)[tid];
    float4 b4 = ((const float4*)beta)[tid];
    float4 o4;
    o4.x = (v.x - mu) * rstd * g4.x + b4.x;
    o4.y = (v.y - mu) * rstd * g4.y + b4.y;
    o4.z = (v.z - mu) * rstd * g4.z + b4.z;
    o4.w = (v.w - mu) * rstd * g4.w + b4.w;
    ((float4*)(out + (size_t)row * DIM))[tid] = o4;
}

// ---------------------------------------------------------------------------
// Tiled fp32 GEMM:  C[M,N] = A[M,K] @ W[N,K]^T + bias  (+ epilogue)
//   BM=BN=128, BK=16, 256 threads, 8x8 register micro-tile per thread.
// EPI: 0 = bias only; 1 = GELU(bias+..); 2 = bias + residual add
// ---------------------------------------------------------------------------
#define EPI_BIAS 0
#define EPI_GELU 1
#define EPI_RES  2

template<int EPI>
__global__ __launch_bounds__(256)
void gemm_kernel(const float* __restrict__ A,
                 const float* __restrict__ W,
                 const float* __restrict__ bias,
                 const float* __restrict__ res,
                 float* __restrict__ C,
                 int M, int N, int K)
{
    const int BM = 128, BN = 128, BK = 16;
    __shared__ float As[BK][BM + 4];
    __shared__ float Bs[BK][BN + 4];

    int t  = threadIdx.x;
    int tx = t & 15;          // 0..15 -> N direction
    int ty = t >> 4;          // 0..15 -> M direction
    int m0 = blockIdx.y * BM;
    int n0 = blockIdx.x * BN;

    float acc[8][8];
    #pragma unroll
    for (int i = 0; i < 8; i++)
        #pragma unroll
        for (int j = 0; j < 8; j++) acc[i][j] = 0.0f;

    for (int k0 = 0; k0 < K; k0 += BK) {
        // Load 128x16 A tile and 128x16 W tile, transposed into smem.
        #pragma unroll
        for (int l = 0; l < 2; l++) {
            int f   = t + l * 256;         // float4 id, 0..511
            int row = f >> 2;              // 0..127
            int kg  = (f & 3) << 2;        // 0,4,8,12
            float4 a4 = *(const float4*)(A + (size_t)(m0 + row) * K + k0 + kg);
            As[kg + 0][row] = a4.x;
            As[kg + 1][row] = a4.y;
            As[kg + 2][row] = a4.z;
            As[kg + 3][row] = a4.w;
            float4 b4 = *(const float4*)(W + (size_t)(n0 + row) * K + k0 + kg);
            Bs[kg + 0][row] = b4.x;
            Bs[kg + 1][row] = b4.y;
            Bs[kg + 2][row] = b4.z;
            Bs[kg + 3][row] = b4.w;
        }
        __syncthreads();

        #pragma unroll
        for (int kk = 0; kk < BK; kk++) {
            float a[8], b[8];
            *(float4*)&a[0] = *(const float4*)&As[kk][ty * 8];
            *(float4*)&a[4] = *(const float4*)&As[kk][ty * 8 + 4];
            *(float4*)&b[0] = *(const float4*)&Bs[kk][tx * 8];
            *(float4*)&b[4] = *(const float4*)&Bs[kk][tx * 8 + 4];
            #pragma unroll
            for (int i = 0; i < 8; i++)
                #pragma unroll
                for (int j = 0; j < 8; j++)
                    acc[i][j] += a[i] * b[j];
        }
        __syncthreads();
    }

    // Epilogue
    #pragma unroll
    for (int i = 0; i < 8; i++) {
        int row = m0 + ty * 8 + i;
        #pragma unroll
        for (int j = 0; j < 8; j++) {
            int col = n0 + tx * 8 + j;
            float v = acc[i][j] + bias[col];
            if (EPI == EPI_GELU) {
                v = 0.5f * v * (1.0f + erff(v * 0.70710678118654752f));
            } else if (EPI == EPI_RES) {
                v += res[(size_t)row * N + col];
            }
            C[(size_t)row * N + col] = v;
        }
    }
}

// ---------------------------------------------------------------------------
// Causal attention, one block per (b, h, q) row.
//   Scores for all keys 0..q live in smem (max 2048 floats = 8 KB).
//   Two-pass softmax, then weighted V accumulation.
// qkv layout per token row (3072): [ q(1024) | k(1024) | v(1024) ], head h at +h*64
// ---------------------------------------------------------------------------
__global__ __launch_bounds__(128)
void attn_kernel(const float* __restrict__ qkv, float* __restrict__ out)
{
    int qi = blockIdx.x;       // query position 0..2047
    int h  = blockIdx.y;       // head
    int b  = blockIdx.z;       // batch
    int tid = threadIdx.x;     // 128

    __shared__ float sq[HDIM];
    __shared__ float ss[SEQ];
    __shared__ float red[128];

    const float* base = qkv + (size_t)b * SEQ * QKV_DIM;
    const float* qv   = base + (size_t)qi * QKV_DIM + h * HDIM;

    if (tid < HDIM / 4)
        ((float4*)sq)[tid] = ((const float4*)qv)[tid];
    __syncthreads();

    int nk = qi + 1;

    // Pass 1: scores
    float lmax = -1e30f;
    for (int j = tid; j < nk; j += 128) {
        const float4* kv = (const float4*)(base + (size_t)j * QKV_DIM + DIM + h * HDIM);
        float s = 0.0f;
        #pragma unroll
        for (int u = 0; u < HDIM / 4; u++) {
            float4 kk = kv[u];
            float4 qq = ((const float4*)sq)[u];
            s += qq.x * kk.x + qq.y * kk.y + qq.z * kk.z + qq.w * kk.w;
        }
        s *= 0.125f;               // 1/sqrt(64)
        ss[j] = s;
        lmax = fmaxf(lmax, s);
    }

    // Reduce max
    red[tid] = lmax;
    __syncthreads();
    #pragma unroll
    for (int o = 64; o > 0; o >>= 1) {
        if (tid < o) red[tid] = fmaxf(red[tid], red[tid + o]);
        __syncthreads();
    }
    float mx = red[0];
    __syncthreads();

    // Exponentiate + sum
    float lsum = 0.0f;
    for (int j = tid; j < nk; j += 128) {
        float e = expf(ss[j] - mx);
        ss[j] = e;
        lsum += e;
    }
    red[tid] = lsum;
    __syncthreads();
    #pragma unroll
    for (int o = 64; o > 0; o >>= 1) {
        if (tid < o) red[tid] += red[tid + o];
        __syncthreads();
    }
    float inv = 1.0f / red[0];
    __syncthreads();

    // Pass 2: weighted V sum. 128 threads = 64 dims x 2 key partitions.
    int d    = tid & 63;
    int part = tid >> 6;
    const float* vbase = base + 2 * DIM + h * HDIM + d;
    float acc = 0.0f;
    for (int j = part; j < nk; j += 2)
        acc += ss[j] * vbase[(size_t)j * QKV_DIM];

    red[tid] = acc;
    __syncthreads();
    if (tid < 64)
        out[((size_t)(b * SEQ + qi)) * DIM + h * HDIM + tid] =
            (red[tid] + red[tid + 64]) * inv;
}

// ---------------------------------------------------------------------------
// Launcher
// ---------------------------------------------------------------------------
extern "C" void kernel_launch(void* const* d_in, const int* in_sizes, int n_in,
                              void* d_out, int out_size)
{
    const float* x      = (const float*)d_in[0];
    const float* qkv_w  = (const float*)d_in[1];
    const float* qkv_b  = (const float*)d_in[2];
    const float* proj_w = (const float*)d_in[3];
    const float* proj_b = (const float*)d_in[4];
    const float* ff1_w  = (const float*)d_in[5];
    const float* ff1_b  = (const float*)d_in[6];
    const float* ff2_w  = (const float*)d_in[7];
    const float* ff2_b  = (const float*)d_in[8];
    const float* ln1_g  = (const float*)d_in[9];
    const float* ln1_b  = (const float*)d_in[10];
    const float* ln2_g  = (const float*)d_in[11];
    const float* ln2_b  = (const float*)d_in[12];
    float* out = (float*)d_out;

    float *xn, *qkv, *att, *x1, *hbuf;
    cudaGetSymbolAddress((void**)&xn,   g_xn);
    cudaGetSymbolAddress((void**)&qkv,  g_qkv);
    cudaGetSymbolAddress((void**)&att,  g_att);
    cudaGetSymbolAddress((void**)&x1,   g_x1);
    cudaGetSymbolAddress((void**)&hbuf, g_h);

    // 1. LN1
    ln_kernel<<<TOKENS, 256>>>(x, ln1_g, ln1_b, xn);

    // 2. QKV projection: [4096,3072] = xn @ qkv_w^T + b
    {
        dim3 grid(QKV_DIM / 128, TOKENS / 128);
        gemm_kernel<EPI_BIAS><<<grid, 256>>>(xn, qkv_w, qkv_b, nullptr, qkv,
                                             TOKENS, QKV_DIM, DIM);
    }

    // 3. Causal attention
    {
        dim3 grid(SEQ, NHEAD, BATCH);
        attn_kernel<<<grid, 128>>>(qkv, att);
    }

    // 4. proj + residual: x1 = x + att @ proj_w^T + proj_b
    {
        dim3 grid(DIM / 128, TOKENS / 128);
        gemm_kernel<EPI_RES><<<grid, 256>>>(att, proj_w, proj_b, x, x1,
                                            TOKENS, DIM, DIM);
    }

    // 5. LN2
    ln_kernel<<<TOKENS, 256>>>(x1, ln2_g, ln2_b, xn);

    // 6. FF1 + exact GELU: h = gelu(xn @ ff1_w^T + b1), [4096,4096]
    {
        dim3 grid(HIDDEN / 128, TOKENS / 128);
        gemm_kernel<EPI_GELU><<<grid, 256>>>(xn, ff1_w, ff1_b, nullptr, hbuf,
                                             TOKENS, HIDDEN, DIM);
    }

    // 7. FF2 + residual into d_out: out = x1 + h @ ff2_w^T + b2
    {
        dim3 grid(DIM / 128, TOKENS / 128);
        gemm_kernel<EPI_RES><<<grid, 256>>>(hbuf, ff2_w, ff2_b, x1, out,
                                            TOKENS, DIM, HIDDEN);
    }
}

// round 2
// speedup vs baseline: 2.2378x; 2.2378x over previous
#include <cuda_runtime.h>
#include <cuda_bf16.h>
#include <math.h>

// ---------------------------------------------------------------------------
// Problem constants
// ---------------------------------------------------------------------------
#define BATCH    2
#define SEQ      2048
#define DIM      1024
#define NHEAD    16
#define HDIM     64
#define HIDDEN   4096
#define TOKENS   (BATCH * SEQ)          // 4096
#define QKV_DIM  (3 * DIM)              // 3072
#define LN_EPS   1e-5f

// ---------------------------------------------------------------------------
// Scratch buffers
// ---------------------------------------------------------------------------
__device__ float g_xn [TOKENS * DIM];
__device__ float g_qkv[TOKENS * QKV_DIM];
__device__ float g_att[TOKENS * DIM];
__device__ float g_x1 [TOKENS * DIM];
__device__ float g_h  [TOKENS * HIDDEN];

// ---------------------------------------------------------------------------
// LayerNorm
// ---------------------------------------------------------------------------
__global__ void ln_kernel(const float* __restrict__ in,
                          const float* __restrict__ gamma,
                          const float* __restrict__ beta,
                          float* __restrict__ out)
{
    int row = blockIdx.x;
    int tid = threadIdx.x;               // 256
    const float4* rp = (const float4*)(in + (size_t)row * DIM);
    float4 v = rp[tid];

    float s  = v.x + v.y + v.z + v.w;
    float s2 = v.x*v.x + v.y*v.y + v.z*v.z + v.w*v.w;

    __shared__ float rs[256];
    __shared__ float rq[256];
    rs[tid] = s; rq[tid] = s2;
    __syncthreads();
    #pragma unroll
    for (int o = 128; o > 0; o >>= 1) {
        if (tid < o) { rs[tid] += rs[tid + o]; rq[tid] += rq[tid + o]; }
        __syncthreads();
    }
    float mu  = rs[0] * (1.0f / DIM);
    float var = rq[0] * (1.0f / DIM) - mu * mu;
    float rstd = rsqrtf(var + LN_EPS);

    float4 g4 = ((const float4*)gamma)[tid];
    float4 b4 = ((const float4*)beta)[tid];
    float4 o4;
    o4.x = (v.x - mu) * rstd * g4.x + b4.x;
    o4.y = (v.y - mu) * rstd * g4.y + b4.y;
    o4.z = (v.z - mu) * rstd * g4.z + b4.z;
    o4.w = (v.w - mu) * rstd * g4.w + b4.w;
    ((float4*)(out + (size_t)row * DIM))[tid] = o4;
}

// ---------------------------------------------------------------------------
// Tiled fp32 GEMM with register prefetch (software pipeline):
//   C[M,N] = A[M,K] @ W[N,K]^T + bias (+ epilogue)
// ---------------------------------------------------------------------------
#define EPI_BIAS 0
#define EPI_GELU 1
#define EPI_RES  2

template<int EPI>
__global__ __launch_bounds__(256)
void gemm_kernel(const float* __restrict__ A,
                 const float* __restrict__ W,
                 const float* __restrict__ bias,
                 const float* __restrict__ res,
                 float* __restrict__ C,
                 int M, int N, int K)
{
    const int BM = 128, BN = 128, BK = 16;
    __shared__ float As[BK][BM + 4];
    __shared__ float Bs[BK][BN + 4];

    int t  = threadIdx.x;
    int tx = t & 15;
    int ty = t >> 4;
    int m0 = blockIdx.y * BM;
    int n0 = blockIdx.x * BN;

    // global load coords (2 float4 per thread per operand tile)
    int f0   = t;            int row0 = f0 >> 2; int kg0 = (f0 & 3) << 2;
    int f1   = t + 256;      int row1 = f1 >> 2; int kg1 = (f1 & 3) << 2;

    float acc[8][8];
    #pragma unroll
    for (int i = 0; i < 8; i++)
        #pragma unroll
        for (int j = 0; j < 8; j++) acc[i][j] = 0.0f;

    // prefetch first tile
    float4 pa0 = *(const float4*)(A + (size_t)(m0 + row0) * K + kg0);
    float4 pa1 = *(const float4*)(A + (size_t)(m0 + row1) * K + kg1);
    float4 pb0 = *(const float4*)(W + (size_t)(n0 + row0) * K + kg0);
    float4 pb1 = *(const float4*)(W + (size_t)(n0 + row1) * K + kg1);

    for (int k0 = 0; k0 < K; k0 += BK) {
        As[kg0 + 0][row0] = pa0.x; As[kg0 + 1][row0] = pa0.y;
        As[kg0 + 2][row0] = pa0.z; As[kg0 + 3][row0] = pa0.w;
        As[kg1 + 0][row1] = pa1.x; As[kg1 + 1][row1] = pa1.y;
        As[kg1 + 2][row1] = pa1.z; As[kg1 + 3][row1] = pa1.w;
        Bs[kg0 + 0][row0] = pb0.x; Bs[kg0 + 1][row0] = pb0.y;
        Bs[kg0 + 2][row0] = pb0.z; Bs[kg0 + 3][row0] = pb0.w;
        Bs[kg1 + 0][row1] = pb1.x; Bs[kg1 + 1][row1] = pb1.y;
        Bs[kg1 + 2][row1] = pb1.z; Bs[kg1 + 3][row1] = pb1.w;
        __syncthreads();

        int kn = k0 + BK;
        if (kn < K) {
            pa0 = *(const float4*)(A + (size_t)(m0 + row0) * K + kn + kg0);
            pa1 = *(const float4*)(A + (size_t)(m0 + row1) * K + kn + kg1);
            pb0 = *(const float4*)(W + (size_t)(n0 + row0) * K + kn + kg0);
            pb1 = *(const float4*)(W + (size_t)(n0 + row1) * K + kn + kg1);
        }

        #pragma unroll
        for (int kk = 0; kk < BK; kk++) {
            float a[8], b[8];
            *(float4*)&a[0] = *(const float4*)&As[kk][ty * 8];
            *(float4*)&a[4] = *(const float4*)&As[kk][ty * 8 + 4];
            *(float4*)&b[0] = *(const float4*)&Bs[kk][tx * 8];
            *(float4*)&b[4] = *(const float4*)&Bs[kk][tx * 8 + 4];
            #pragma unroll
            for (int i = 0; i < 8; i++)
                #pragma unroll
                for (int j = 0; j < 8; j++)
                    acc[i][j] += a[i] * b[j];
        }
        __syncthreads();
    }

    #pragma unroll
    for (int i = 0; i < 8; i++) {
        int row = m0 + ty * 8 + i;
        #pragma unroll
        for (int j = 0; j < 8; j++) {
            int col = n0 + tx * 8 + j;
            float v = acc[i][j] + bias[col];
            if (EPI == EPI_GELU) {
                v = 0.5f * v * (1.0f + erff(v * 0.70710678118654752f));
            } else if (EPI == EPI_RES) {
                v += res[(size_t)row * N + col];
            }
            C[(size_t)row * N + col] = v;
        }
    }
}

// ---------------------------------------------------------------------------
// Flash attention: one block per (b, h, 64-query tile). 256 threads.
// Online softmax, K/V streamed tile-by-tile through smem, O in registers.
//   Thread (ty,tx), ty=t/16, tx=t%16: owns q rows ty*4+i, k cols / dims tx*4+j.
// Dynamic smem: Qt[64][68] (d-major, scaled), Kt[64][68] (d-major),
//               Vs[64][68] (k-major), Pt[64][68] (k-major).
// ---------------------------------------------------------------------------
#define FA_PAD 68
#define FA_SMEM (4 * 64 * FA_PAD * sizeof(float))   // 69632 B

__global__ __launch_bounds__(256)
void flash_kernel(const float* __restrict__ qkv, float* __restrict__ out)
{
    extern __shared__ float sm[];
    float* Qt = sm;
    float* Kt = sm + 64 * FA_PAD;
    float* Vs = sm + 2 * 64 * FA_PAD;
    float* Pt = sm + 3 * 64 * FA_PAD;

    int qt = gridDim.x - 1 - blockIdx.x;   // longest tiles scheduled first
    int h  = blockIdx.y;
    int b  = blockIdx.z;
    int t  = threadIdx.x;
    int tx = t & 15;
    int ty = t >> 4;

    const float* base = qkv + (size_t)b * SEQ * QKV_DIM;

    // ---- load Q tile, transposed + pre-scaled by 1/sqrt(64) ----
    {
        int r  = t >> 2;            // 0..63 : q row within tile
        int ds = (t & 3) << 4;      // 0,16,32,48 : d chunk start
        const float* qrow = base + (size_t)(qt * 64 + r) * QKV_DIM + h * HDIM + ds;
        #pragma unroll
        for (int u = 0; u < 4; u++) {
            float4 v = ((const float4*)qrow)[u];
            int d = ds + u * 4;
            Qt[(d + 0) * FA_PAD + r] = v.x * 0.125f;
            Qt[(d + 1) * FA_PAD + r] = v.y * 0.125f;
            Qt[(d + 2) * FA_PAD + r] = v.z * 0.125f;
            Qt[(d + 3) * FA_PAD + r] = v.w * 0.125f;
        }
    }

    float m[4], l[4], o[4][4];
    #pragma unroll
    for (int i = 0; i < 4; i++) {
        m[i] = -1e30f; l[i] = 0.0f;
        #pragma unroll
        for (int j = 0; j < 4; j++) o[i][j] = 0.0f;
    }

    for (int kt = 0; kt <= qt; kt++) {
        __syncthreads();   // previous iteration done with Kt/Vs/Pt
        // ---- load K (transposed) and V (direct) tiles ----
        {
            int r  = t >> 2;
            int ds = (t & 3) << 4;
            const float* krow = base + (size_t)(kt * 64 + r) * QKV_DIM + DIM + h * HDIM + ds;
            const float* vrow = krow + DIM;
            #pragma unroll
            for (int u = 0; u < 4; u++) {
                float4 kv = ((const float4*)krow)[u];
                int d = ds + u * 4;
                Kt[(d + 0) * FA_PAD + r] = kv.x;
                Kt[(d + 1) * FA_PAD + r] = kv.y;
                Kt[(d + 2) * FA_PAD + r] = kv.z;
                Kt[(d + 3) * FA_PAD + r] = kv.w;
                ((float4*)(Vs + r * FA_PAD + ds))[u] = ((const float4*)vrow)[u];
            }
        }
        __syncthreads();

        // ---- S = Q K^T (per-thread 4x4) ----
        float s[4][4];
        #pragma unroll
        for (int i = 0; i < 4; i++)
            #pragma unroll
            for (int j = 0; j < 4; j++) s[i][j] = 0.0f;

        #pragma unroll 8
        for (int d = 0; d < 64; d++) {
            float4 a4 = *(const float4*)(Qt + d * FA_PAD + ty * 4);
            float4 b4 = *(const float4*)(Kt + d * FA_PAD + tx * 4);
            float a[4] = {a4.x, a4.y, a4.z, a4.w};
            float bb[4] = {b4.x, b4.y, b4.z, b4.w};
            #pragma unroll
            for (int i = 0; i < 4; i++)
                #pragma unroll
                for (int j = 0; j < 4; j++)
                    s[i][j] += a[i] * bb[j];
        }

        // ---- causal mask on diagonal tile ----
        if (kt == qt) {
            #pragma unroll
            for (int i = 0; i < 4; i++)
                #pragma unroll
                for (int j = 0; j < 4; j++)
                    if (tx * 4 + j > ty * 4 + i) s[i][j] = -1e30f;
        }

        // ---- online softmax update ----
        #pragma unroll
        for (int i = 0; i < 4; i++) {
            float rm = fmaxf(fmaxf(s[i][0], s[i][1]), fmaxf(s[i][2], s[i][3]));
            #pragma unroll
            for (int w = 1; w < 16; w <<= 1)
                rm = fmaxf(rm, __shfl_xor_sync(0xffffffffu, rm, w));
            float mnew = fmaxf(m[i], rm);
            float alpha = __expf(m[i] - mnew);
            float rs = 0.0f;
            #pragma unroll
            for (int j = 0; j < 4; j++) {
                float p = __expf(s[i][j] - mnew);
                Pt[(tx * 4 + j) * FA_PAD + ty * 4 + i] = p;
                rs += p;
            }
            #pragma unroll
            for (int w = 1; w < 16; w <<= 1)
                rs += __shfl_xor_sync(0xffffffffu, rs, w);
            l[i] = l[i] * alpha + rs;
            m[i] = mnew;
            #pragma unroll
            for (int j = 0; j < 4; j++) o[i][j] *= alpha;
        }
        __syncthreads();   // Pt visible

        // ---- O += P @ V ----
        #pragma unroll 8
        for (int k = 0; k < 64; k++) {
            float4 a4 = *(const float4*)(Pt + k * FA_PAD + ty * 4);
            float4 b4 = *(const float4*)(Vs + k * FA_PAD + tx * 4);
            float a[4] = {a4.x, a4.y, a4.z, a4.w};
            float bb[4] = {b4.x, b4.y, b4.z, b4.w};
            #pragma unroll
            for (int i = 0; i < 4; i++)
                #pragma unroll
                for (int j = 0; j < 4; j++)
                    o[i][j] += a[i] * bb[j];
        }
    }

    // ---- epilogue: normalize and write ----
    #pragma unroll
    for (int i = 0; i < 4; i++) {
        float inv = 1.0f / l[i];
        int row = qt * 64 + ty * 4 + i;
        float4 w4;
        w4.x = o[i][0] * inv; w4.y = o[i][1] * inv;
        w4.z = o[i][2] * inv; w4.w = o[i][3] * inv;
        *(float4*)(out + (size_t)(b * SEQ + row) * DIM + h * HDIM + tx * 4) = w4;
    }
}

// ---------------------------------------------------------------------------
// Launcher
// ---------------------------------------------------------------------------
extern "C" void kernel_launch(void* const* d_in, const int* in_sizes, int n_in,
                              void* d_out, int out_size)
{
    const float* x      = (const float*)d_in[0];
    const float* qkv_w  = (const float*)d_in[1];
    const float* qkv_b  = (const float*)d_in[2];
    const float* proj_w = (const float*)d_in[3];
    const float* proj_b = (const float*)d_in[4];
    const float* ff1_w  = (const float*)d_in[5];
    const float* ff1_b  = (const float*)d_in[6];
    const float* ff2_w  = (const float*)d_in[7];
    const float* ff2_b  = (const float*)d_in[8];
    const float* ln1_g  = (const float*)d_in[9];
    const float* ln1_b  = (const float*)d_in[10];
    const float* ln2_g  = (const float*)d_in[11];
    const float* ln2_b  = (const float*)d_in[12];
    float* out = (float*)d_out;

    float *xn, *qkv, *att, *x1, *hbuf;
    cudaGetSymbolAddress((void**)&xn,   g_xn);
    cudaGetSymbolAddress((void**)&qkv,  g_qkv);
    cudaGetSymbolAddress((void**)&att,  g_att);
    cudaGetSymbolAddress((void**)&x1,   g_x1);
    cudaGetSymbolAddress((void**)&hbuf, g_h);

    cudaFuncSetAttribute(flash_kernel,
                         cudaFuncAttributeMaxDynamicSharedMemorySize, FA_SMEM);

    // 1. LN1
    ln_kernel<<<TOKENS, 256>>>(x, ln1_g, ln1_b, xn);

    // 2. QKV projection
    {
        dim3 grid(QKV_DIM / 128, TOKENS / 128);
        gemm_kernel<EPI_BIAS><<<grid, 256>>>(xn, qkv_w, qkv_b, nullptr, qkv,
                                             TOKENS, QKV_DIM, DIM);
    }

    // 3. Flash causal attention
    {
        dim3 grid(SEQ / 64, NHEAD, BATCH);
        flash_kernel<<<grid, 256, FA_SMEM>>>(qkv, att);
    }

    // 4. proj + residual
    {
        dim3 grid(DIM / 128, TOKENS / 128);
        gemm_kernel<EPI_RES><<<grid, 256>>>(att, proj_w, proj_b, x, x1,
                                            TOKENS, DIM, DIM);
    }

    // 5. LN2
    ln_kernel<<<TOKENS, 256>>>(x1, ln2_g, ln2_b, xn);

    // 6. FF1 + GELU
    {
        dim3 grid(HIDDEN / 128, TOKENS / 128);
        gemm_kernel<EPI_GELU><<<grid, 256>>>(xn, ff1_w, ff1_b, nullptr, hbuf,
                                             TOKENS, HIDDEN, DIM);
    }

    // 7. FF2 + residual
    {
        dim3 grid(DIM / 128, TOKENS / 128);
        gemm_kernel<EPI_RES><<<grid, 256>>>(hbuf, ff2_w, ff2_b, x1, out,
                                            TOKENS, DIM, HIDDEN);
    }
}

// round 4
// speedup vs baseline: 3.9345x; 1.7582x over previous
#include <cuda_runtime.h>
#include <cuda_bf16.h>
#include <math.h>
#include <stdint.h>

// ---------------------------------------------------------------------------
// Problem constants
// ---------------------------------------------------------------------------
#define BATCH    2
#define SEQ      2048
#define DIM      1024
#define NHEAD    16
#define HDIM     64
#define HIDDEN   4096
#define TOKENS   (BATCH * SEQ)          // 4096
#define QKV_DIM  (3 * DIM)              // 3072
#define LN_EPS   1e-5f

// ---------------------------------------------------------------------------
// Scratch buffers
// ---------------------------------------------------------------------------
__device__ float g_xn [TOKENS * DIM];
__device__ float g_qkv[TOKENS * QKV_DIM];
__device__ float g_att[TOKENS * DIM];
__device__ float g_x1 [TOKENS * DIM];
__device__ float g_h  [TOKENS * HIDDEN];

// ---------------------------------------------------------------------------
// LayerNorm
// ---------------------------------------------------------------------------
__global__ void ln_kernel(const float* __restrict__ in,
                          const float* __restrict__ gamma,
                          const float* __restrict__ beta,
                          float* __restrict__ out)
{
    int row = blockIdx.x;
    int tid = threadIdx.x;               // 256
    const float4* rp = (const float4*)(in + (size_t)row * DIM);
    float4 v = rp[tid];

    float s  = v.x + v.y + v.z + v.w;
    float s2 = v.x*v.x + v.y*v.y + v.z*v.z + v.w*v.w;

    __shared__ float rs[256];
    __shared__ float rq[256];
    rs[tid] = s; rq[tid] = s2;
    __syncthreads();
    #pragma unroll
    for (int o = 128; o > 0; o >>= 1) {
        if (tid < o) { rs[tid] += rs[tid + o]; rq[tid] += rq[tid + o]; }
        __syncthreads();
    }
    float mu  = rs[0] * (1.0f / DIM);
    float var = rq[0] * (1.0f / DIM) - mu * mu;
    float rstd = rsqrtf(var + LN_EPS);

    float4 g4 = ((const float4*)gamma)[tid];
    float4 b4 = ((const float4*)beta)[tid];
    float4 o4;
    o4.x = (v.x - mu) * rstd * g4.x + b4.x;
    o4.y = (v.y - mu) * rstd * g4.y + b4.y;
    o4.z = (v.z - mu) * rstd * g4.z + b4.z;
    o4.w = (v.w - mu) * rstd * g4.w + b4.w;
    ((float4*)(out + (size_t)row * DIM))[tid] = o4;
}

// ---------------------------------------------------------------------------
// TF32 tensor-core GEMM:  C[M,N] = A[M,K] @ W[N,K]^T + bias (+ epilogue)
//   BM=BN=128, BK=16. 256 threads = 8 warps, warp grid 2(m) x 4(n),
//   warp tile 64x32 = 4x4 fragments of m16n8k8.
//   Values converted to tf32 (round-to-nearest) on the way into smem.
// ---------------------------------------------------------------------------
#define EPI_BIAS 0
#define EPI_GELU 1
#define EPI_RES  2

__device__ __forceinline__ uint32_t f2tf32(float x)
{
    uint32_t r;
    asm("cvt.rna.tf32.f32 %0, %1;" : "=r"(r) : "f"(x));
    return r;
}

__device__ __forceinline__ void mma_tf32(float c[4],
                                         const uint32_t a[4],
                                         const uint32_t b[2])
{
    asm volatile(
        "mma.sync.aligned.m16n8k8.row.col.f32.tf32.tf32.f32 "
        "{%0,%1,%2,%3}, {%4,%5,%6,%7}, {%8,%9}, {%0,%1,%2,%3};"
        : "+f"(c[0]), "+f"(c[1]), "+f"(c[2]), "+f"(c[3])
        : "r"(a[0]), "r"(a[1]), "r"(a[2]), "r"(a[3]),
          "r"(b[0]), "r"(b[1]));
}

#define GK_PAD 20   // 16 + 4 pad -> conflict-free fragment loads

template<int EPI>
__global__ __launch_bounds__(256, 2)
void gemm_tf32_kernel(const float* __restrict__ A,
                      const float* __restrict__ W,
                      const float* __restrict__ bias,
                      const float* __restrict__ res,
                      float* __restrict__ C,
                      int M, int N, int K)
{
    __shared__ uint32_t As[128][GK_PAD];
    __shared__ uint32_t Bs[128][GK_PAD];

    int t    = threadIdx.x;
    int lane = t & 31;
    int wid  = t >> 5;
    int gid  = lane >> 2;      // 0..7
    int tig  = lane & 3;       // 0..3
    int warpM = (wid >> 2) * 64;   // 0 or 64
    int warpN = (wid & 3) * 32;    // 0,32,64,96
    int m0 = blockIdx.y * 128;
    int n0 = blockIdx.x * 128;

    // global load ids: thread handles rows r0 and r0+64, k-chunk kc..kc+3
    int r0 = t >> 2;
    int kc = (t & 3) << 2;

    float acc[4][4][4];
    #pragma unroll
    for (int im = 0; im < 4; im++)
        #pragma unroll
        for (int jn = 0; jn < 4; jn++)
            #pragma unroll
            for (int r = 0; r < 4; r++) acc[im][jn][r] = 0.0f;

    // prefetch first k-tile
    float4 pa0 = *(const float4*)(A + (size_t)(m0 + r0) * K + kc);
    float4 pa1 = *(const float4*)(A + (size_t)(m0 + r0 + 64) * K + kc);
    float4 pb0 = *(const float4*)(W + (size_t)(n0 + r0) * K + kc);
    float4 pb1 = *(const float4*)(W + (size_t)(n0 + r0 + 64) * K + kc);

    for (int k0 = 0; k0 < K; k0 += 16) {
        As[r0][kc+0] = f2tf32(pa0.x); As[r0][kc+1] = f2tf32(pa0.y);
        As[r0][kc+2] = f2tf32(pa0.z); As[r0][kc+3] = f2tf32(pa0.w);
        As[r0+64][kc+0] = f2tf32(pa1.x); As[r0+64][kc+1] = f2tf32(pa1.y);
        As[r0+64][kc+2] = f2tf32(pa1.z); As[r0+64][kc+3] = f2tf32(pa1.w);
        Bs[r0][kc+0] = f2tf32(pb0.x); Bs[r0][kc+1] = f2tf32(pb0.y);
        Bs[r0][kc+2] = f2tf32(pb0.z); Bs[r0][kc+3] = f2tf32(pb0.w);
        Bs[r0+64][kc+0] = f2tf32(pb1.x); Bs[r0+64][kc+1] = f2tf32(pb1.y);
        Bs[r0+64][kc+2] = f2tf32(pb1.z); Bs[r0+64][kc+3] = f2tf32(pb1.w);
        __syncthreads();

        int kn = k0 + 16;
        if (kn < K) {
            pa0 = *(const float4*)(A + (size_t)(m0 + r0) * K + kn + kc);
            pa1 = *(const float4*)(A + (size_t)(m0 + r0 + 64) * K + kn + kc);
            pb0 = *(const float4*)(W + (size_t)(n0 + r0) * K + kn + kc);
            pb1 = *(const float4*)(W + (size_t)(n0 + r0 + 64) * K + kn + kc);
        }

        #pragma unroll
        for (int ks = 0; ks < 2; ks++) {
            int kb = ks * 8;
            uint32_t af[4][4];
            #pragma unroll
            for (int im = 0; im < 4; im++) {
                int mr = warpM + im * 16 + gid;
                af[im][0] = As[mr    ][kb + tig];
                af[im][1] = As[mr + 8][kb + tig];
                af[im][2] = As[mr    ][kb + tig + 4];
                af[im][3] = As[mr + 8][kb + tig + 4];
            }
            uint32_t bf[4][2];
            #pragma unroll
            for (int jn = 0; jn < 4; jn++) {
                int nr = warpN + jn * 8 + gid;
                bf[jn][0] = Bs[nr][kb + tig];
                bf[jn][1] = Bs[nr][kb + tig + 4];
            }
            #pragma unroll
            for (int im = 0; im < 4; im++)
                #pragma unroll
                for (int jn = 0; jn < 4; jn++)
                    mma_tf32(acc[im][jn], af[im], bf[jn]);
        }
        __syncthreads();
    }

    // Epilogue. Accumulator mapping (m16n8):
    //   c0,c1 -> row = gid,   cols = 2*tig, 2*tig+1
    //   c2,c3 -> row = gid+8, same cols
    #pragma unroll
    for (int im = 0; im < 4; im++) {
        #pragma unroll
        for (int jn = 0; jn < 4; jn++) {
            int col = n0 + warpN + jn * 8 + tig * 2;
            float b0v = bias[col], b1v = bias[col + 1];
            #pragma unroll
            for (int half = 0; half < 2; half++) {
                int row = m0 + warpM + im * 16 + gid + half * 8;
                float v0 = acc[im][jn][half * 2 + 0] + b0v;
                float v1 = acc[im][jn][half * 2 + 1] + b1v;
                if (EPI == EPI_GELU) {
                    v0 = 0.5f * v0 * (1.0f + erff(v0 * 0.70710678118654752f));
                    v1 = 0.5f * v1 * (1.0f + erff(v1 * 0.70710678118654752f));
                } else if (EPI == EPI_RES) {
                    float2 rr = *(const float2*)(res + (size_t)row * N + col);
                    v0 += rr.x; v1 += rr.y;
                }
                float2 o2; o2.x = v0; o2.y = v1;
                *(float2*)(C + (size_t)row * N + col) = o2;
            }
        }
    }
}

// ---------------------------------------------------------------------------
// Flash attention: one block per (b, h, 64-query tile). 256 threads.
// ---------------------------------------------------------------------------
#define FA_PAD 68
#define FA_SMEM (4 * 64 * FA_PAD * sizeof(float))   // 69632 B

__global__ __launch_bounds__(256)
void flash_kernel(const float* __restrict__ qkv, float* __restrict__ out)
{
    extern __shared__ float sm[];
    float* Qt = sm;
    float* Kt = sm + 64 * FA_PAD;
    float* Vs = sm + 2 * 64 * FA_PAD;
    float* Pt = sm + 3 * 64 * FA_PAD;

    int qt = gridDim.x - 1 - blockIdx.x;
    int h  = blockIdx.y;
    int b  = blockIdx.z;
    int t  = threadIdx.x;
    int tx = t & 15;
    int ty = t >> 4;

    const float* base = qkv + (size_t)b * SEQ * QKV_DIM;

    {
        int r  = t >> 2;
        int ds = (t & 3) << 4;
        const float* qrow = base + (size_t)(qt * 64 + r) * QKV_DIM + h * HDIM + ds;
        #pragma unroll
        for (int u = 0; u < 4; u++) {
            float4 v = ((const float4*)qrow)[u];
            int d = ds + u * 4;
            Qt[(d + 0) * FA_PAD + r] = v.x * 0.125f;
            Qt[(d + 1) * FA_PAD + r] = v.y * 0.125f;
            Qt[(d + 2) * FA_PAD + r] = v.z * 0.125f;
            Qt[(d + 3) * FA_PAD + r] = v.w * 0.125f;
        }
    }

    float m[4], l[4], o[4][4];
    #pragma unroll
    for (int i = 0; i < 4; i++) {
        m[i] = -1e30f; l[i] = 0.0f;
        #pragma unroll
        for (int j = 0; j < 4; j++) o[i][j] = 0.0f;
    }

    for (int kt = 0; kt <= qt; kt++) {
        __syncthreads();
        {
            int r  = t >> 2;
            int ds = (t & 3) << 4;
            const float* krow = base + (size_t)(kt * 64 + r) * QKV_DIM + DIM + h * HDIM + ds;
            const float* vrow = krow + DIM;
            #pragma unroll
            for (int u = 0; u < 4; u++) {
                float4 kv = ((const float4*)krow)[u];
                int d = ds + u * 4;
                Kt[(d + 0) * FA_PAD + r] = kv.x;
                Kt[(d + 1) * FA_PAD + r] = kv.y;
                Kt[(d + 2) * FA_PAD + r] = kv.z;
                Kt[(d + 3) * FA_PAD + r] = kv.w;
                ((float4*)(Vs + r * FA_PAD + ds))[u] = ((const float4*)vrow)[u];
            }
        }
        __syncthreads();

        float s[4][4];
        #pragma unroll
        for (int i = 0; i < 4; i++)
            #pragma unroll
            for (int j = 0; j < 4; j++) s[i][j] = 0.0f;

        #pragma unroll 8
        for (int d = 0; d < 64; d++) {
            float4 a4 = *(const float4*)(Qt + d * FA_PAD + ty * 4);
            float4 b4 = *(const float4*)(Kt + d * FA_PAD + tx * 4);
            float a[4] = {a4.x, a4.y, a4.z, a4.w};
            float bb[4] = {b4.x, b4.y, b4.z, b4.w};
            #pragma unroll
            for (int i = 0; i < 4; i++)
                #pragma unroll
                for (int j = 0; j < 4; j++)
                    s[i][j] += a[i] * bb[j];
        }

        if (kt == qt) {
            #pragma unroll
            for (int i = 0; i < 4; i++)
                #pragma unroll
                for (int j = 0; j < 4; j++)
                    if (tx * 4 + j > ty * 4 + i) s[i][j] = -1e30f;
        }

        #pragma unroll
        for (int i = 0; i < 4; i++) {
            float rm = fmaxf(fmaxf(s[i][0], s[i][1]), fmaxf(s[i][2], s[i][3]));
            #pragma unroll
            for (int w = 1; w < 16; w <<= 1)
                rm = fmaxf(rm, __shfl_xor_sync(0xffffffffu, rm, w));
            float mnew = fmaxf(m[i], rm);
            float alpha = __expf(m[i] - mnew);
            float rs = 0.0f;
            #pragma unroll
            for (int j = 0; j < 4; j++) {
                float p = __expf(s[i][j] - mnew);
                Pt[(tx * 4 + j) * FA_PAD + ty * 4 + i] = p;
                rs += p;
            }
            #pragma unroll
            for (int w = 1; w < 16; w <<= 1)
                rs += __shfl_xor_sync(0xffffffffu, rs, w);
            l[i] = l[i] * alpha + rs;
            m[i] = mnew;
            #pragma unroll
            for (int j = 0; j < 4; j++) o[i][j] *= alpha;
        }
        __syncthreads();

        #pragma unroll 8
        for (int k = 0; k < 64; k++) {
            float4 a4 = *(const float4*)(Pt + k * FA_PAD + ty * 4);
            float4 b4 = *(const float4*)(Vs + k * FA_PAD + tx * 4);
            float a[4] = {a4.x, a4.y, a4.z, a4.w};
            float bb[4] = {b4.x, b4.y, b4.z, b4.w};
            #pragma unroll
            for (int i = 0; i < 4; i++)
                #pragma unroll
                for (int j = 0; j < 4; j++)
                    o[i][j] += a[i] * bb[j];
        }
    }

    #pragma unroll
    for (int i = 0; i < 4; i++) {
        float inv = 1.0f / l[i];
        int row = qt * 64 + ty * 4 + i;
        float4 w4;
        w4.x = o[i][0] * inv; w4.y = o[i][1] * inv;
        w4.z = o[i][2] * inv; w4.w = o[i][3] * inv;
        *(float4*)(out + (size_t)(b * SEQ + row) * DIM + h * HDIM + tx * 4) = w4;
    }
}

// ---------------------------------------------------------------------------
// Launcher
// ---------------------------------------------------------------------------
extern "C" void kernel_launch(void* const* d_in, const int* in_sizes, int n_in,
                              void* d_out, int out_size)
{
    const float* x      = (const float*)d_in[0];
    const float* qkv_w  = (const float*)d_in[1];
    const float* qkv_b  = (const float*)d_in[2];
    const float* proj_w = (const float*)d_in[3];
    const float* proj_b = (const float*)d_in[4];
    const float* ff1_w  = (const float*)d_in[5];
    const float* ff1_b  = (const float*)d_in[6];
    const float* ff2_w  = (const float*)d_in[7];
    const float* ff2_b  = (const float*)d_in[8];
    const float* ln1_g  = (const float*)d_in[9];
    const float* ln1_b  = (const float*)d_in[10];
    const float* ln2_g  = (const float*)d_in[11];
    const float* ln2_b  = (const float*)d_in[12];
    float* out = (float*)d_out;

    float *xn, *qkv, *att, *x1, *hbuf;
    cudaGetSymbolAddress((void**)&xn,   g_xn);
    cudaGetSymbolAddress((void**)&qkv,  g_qkv);
    cudaGetSymbolAddress((void**)&att,  g_att);
    cudaGetSymbolAddress((void**)&x1,   g_x1);
    cudaGetSymbolAddress((void**)&hbuf, g_h);

    cudaFuncSetAttribute(flash_kernel,
                         cudaFuncAttributeMaxDynamicSharedMemorySize, FA_SMEM);

    // 1. LN1
    ln_kernel<<<TOKENS, 256>>>(x, ln1_g, ln1_b, xn);

    // 2. QKV projection
    {
        dim3 grid(QKV_DIM / 128, TOKENS / 128);
        gemm_tf32_kernel<EPI_BIAS><<<grid, 256>>>(xn, qkv_w, qkv_b, nullptr, qkv,
                                                  TOKENS, QKV_DIM, DIM);
    }

    // 3. Flash causal attention
    {
        dim3 grid(SEQ / 64, NHEAD, BATCH);
        flash_kernel<<<grid, 256, FA_SMEM>>>(qkv, att);
    }

    // 4. proj + residual
    {
        dim3 grid(DIM / 128, TOKENS / 128);
        gemm_tf32_kernel<EPI_RES><<<grid, 256>>>(att, proj_w, proj_b, x, x1,
                                                 TOKENS, DIM, DIM);
    }

    // 5. LN2
    ln_kernel<<<TOKENS, 256>>>(x1, ln2_g, ln2_b, xn);

    // 6. FF1 + GELU
    {
        dim3 grid(HIDDEN / 128, TOKENS / 128);
        gemm_tf32_kernel<EPI_GELU><<<grid, 256>>>(xn, ff1_w, ff1_b, nullptr, hbuf,
                                                  TOKENS, HIDDEN, DIM);
    }

    // 7. FF2 + residual
    {
        dim3 grid(DIM / 128, TOKENS / 128);
        gemm_tf32_kernel<EPI_RES><<<grid, 256>>>(hbuf, ff2_w, ff2_b, x1, out,
                                                 TOKENS, DIM, HIDDEN);
    }
}

// round 7
// speedup vs baseline: 4.5825x; 1.1647x over previous
#include <cuda_runtime.h>
#include <cuda_bf16.h>
#include <math.h>
#include <stdint.h>

// ---------------------------------------------------------------------------
// Problem constants
// ---------------------------------------------------------------------------
#define BATCH    2
#define SEQ      2048
#define DIM      1024
#define NHEAD    16
#define HDIM     64
#define HIDDEN   4096
#define TOKENS   (BATCH * SEQ)          // 4096
#define QKV_DIM  (3 * DIM)              // 3072
#define LN_EPS   1e-5f

// ---------------------------------------------------------------------------
// Scratch buffers
// ---------------------------------------------------------------------------
__device__ float g_xn [TOKENS * DIM];
__device__ float g_qkv[TOKENS * QKV_DIM];
__device__ float g_att[TOKENS * DIM];
__device__ float g_x1 [TOKENS * DIM];
__device__ float g_h  [TOKENS * HIDDEN];
// tf32-pre-rounded weights
__device__ float g_wq[QKV_DIM * DIM];
__device__ float g_wp[DIM * DIM];
__device__ float g_w1[HIDDEN * DIM];
__device__ float g_w2[DIM * HIDDEN];

__device__ __forceinline__ uint32_t f2tf32(float x)
{
    uint32_t r;
    asm("cvt.rna.tf32.f32 %0, %1;" : "=r"(r) : "f"(x));
    return r;
}
__device__ __forceinline__ float round_tf32(float x)
{
    return __uint_as_float(f2tf32(x));
}

// ---------------------------------------------------------------------------
// Weight pre-rounding: out[i] = tf32_rn(in[i])
// ---------------------------------------------------------------------------
__global__ void round_kernel(const float* __restrict__ in,
                             float* __restrict__ out, int n)
{
    int i = (blockIdx.x * 256 + threadIdx.x) * 4;
    if (i < n) {
        float4 v = *(const float4*)(in + i);
        v.x = round_tf32(v.x); v.y = round_tf32(v.y);
        v.z = round_tf32(v.z); v.w = round_tf32(v.w);
        *(float4*)(out + i) = v;
    }
}

// ---------------------------------------------------------------------------
// LayerNorm (output rounded to tf32 — it only feeds GEMM A operands)
// ---------------------------------------------------------------------------
__global__ void ln_kernel(const float* __restrict__ in,
                          const float* __restrict__ gamma,
                          const float* __restrict__ beta,
                          float* __restrict__ out)
{
    int row = blockIdx.x;
    int tid = threadIdx.x;               // 256
    const float4* rp = (const float4*)(in + (size_t)row * DIM);
    float4 v = rp[tid];

    float s  = v.x + v.y + v.z + v.w;
    float s2 = v.x*v.x + v.y*v.y + v.z*v.z + v.w*v.w;

    __shared__ float rs[256];
    __shared__ float rq[256];
    rs[tid] = s; rq[tid] = s2;
    __syncthreads();
    #pragma unroll
    for (int o = 128; o > 0; o >>= 1) {
        if (tid < o) { rs[tid] += rs[tid + o]; rq[tid] += rq[tid + o]; }
        __syncthreads();
    }
    float mu  = rs[0] * (1.0f / DIM);
    float var = rq[0] * (1.0f / DIM) - mu * mu;
    float rstd = rsqrtf(var + LN_EPS);

    float4 g4 = ((const float4*)gamma)[tid];
    float4 b4 = ((const float4*)beta)[tid];
    float4 o4;
    o4.x = round_tf32((v.x - mu) * rstd * g4.x + b4.x);
    o4.y = round_tf32((v.y - mu) * rstd * g4.y + b4.y);
    o4.z = round_tf32((v.z - mu) * rstd * g4.z + b4.z);
    o4.w = round_tf32((v.w - mu) * rstd * g4.w + b4.w);
    ((float4*)(out + (size_t)row * DIM))[tid] = o4;
}

// ---------------------------------------------------------------------------
// TF32 tensor-core GEMM, cp.async double-buffered, DYNAMIC smem:
//   C[M,N] = A[M,K] @ W[N,K]^T + bias (+ epilogue)
//   BM=BN=128, BK=32, 2-stage smem pipeline. 8 warps, warp tile 64x32,
//   m16n8k8 fragments. A and W must be pre-rounded to tf32 values.
// ---------------------------------------------------------------------------
#define EPI_BIAS 0
#define EPI_GELU 1
#define EPI_RES  2
#define GBK   32
#define GPAD  36
// dynamic smem: 2 stages x (A + B) x 128 rows x GPAD floats
#define GEMM_SMEM (2 * 2 * 128 * GPAD * sizeof(float))   // 73728 B

__device__ __forceinline__ void mma_tf32(float c[4],
                                         const uint32_t a[4],
                                         const uint32_t b[2])
{
    asm volatile(
        "mma.sync.aligned.m16n8k8.row.col.f32.tf32.tf32.f32 "
        "{%0,%1,%2,%3}, {%4,%5,%6,%7}, {%8,%9}, {%0,%1,%2,%3};"
        : "+f"(c[0]), "+f"(c[1]), "+f"(c[2]), "+f"(c[3])
        : "r"(a[0]), "r"(a[1]), "r"(a[2]), "r"(a[3]),
          "r"(b[0]), "r"(b[1]));
}

template<int EPI>
__global__ __launch_bounds__(256, 2)
void gemm_tc_kernel(const float* __restrict__ A,
                    const float* __restrict__ W,
                    const float* __restrict__ bias,
                    const float* __restrict__ res,
                    float* __restrict__ C,
                    int M, int N, int K)
{
    extern __shared__ float smem_g[];
    // layout: As[2][128][GPAD] then Bs[2][128][GPAD]
    float* AsBase = smem_g;
    float* BsBase = smem_g + 2 * 128 * GPAD;
    auto As = [&](int buf, int r, int c) -> float& {
        return AsBase[(buf * 128 + r) * GPAD + c];
    };
    auto Bs = [&](int buf, int r, int c) -> float& {
        return BsBase[(buf * 128 + r) * GPAD + c];
    };

    int t    = threadIdx.x;
    int lane = t & 31;
    int wid  = t >> 5;
    int gid  = lane >> 2;
    int tig  = lane & 3;
    int warpM = (wid >> 2) * 64;
    int warpN = (wid & 3) * 32;
    int m0 = blockIdx.y * 128;
    int n0 = blockIdx.x * 128;

    int lrow = t >> 3;            // 0..31
    int lkc  = (t & 7) << 2;      // 0,4,...,28

    float acc[4][4][4];
    #pragma unroll
    for (int im = 0; im < 4; im++)
        #pragma unroll
        for (int jn = 0; jn < 4; jn++)
            #pragma unroll
            for (int r = 0; r < 4; r++) acc[im][jn][r] = 0.0f;

    const float* agbase = A + (size_t)(m0 + lrow) * K + lkc;
    const float* bgbase = W + (size_t)(n0 + lrow) * K + lkc;

    // issue cp.async copies for k-tile kt into buffer buf
    auto issue = [&](int kt, int buf) {
        const float* ag = agbase + kt * GBK;
        const float* bg = bgbase + kt * GBK;
        #pragma unroll
        for (int p = 0; p < 4; p++) {
            uint32_t da = (uint32_t)__cvta_generic_to_shared(&As(buf, lrow + p * 32, lkc));
            asm volatile("cp.async.cg.shared.global [%0], [%1], 16;\n"
                         :: "r"(da), "l"(ag + (size_t)p * 32 * K));
            uint32_t db = (uint32_t)__cvta_generic_to_shared(&Bs(buf, lrow + p * 32, lkc));
            asm volatile("cp.async.cg.shared.global [%0], [%1], 16;\n"
                         :: "r"(db), "l"(bg + (size_t)p * 32 * K));
        }
        asm volatile("cp.async.commit_group;\n");
    };

    auto compute = [&](int buf) {
        #pragma unroll
        for (int kb = 0; kb < GBK; kb += 8) {
            uint32_t af[4][4];
            #pragma unroll
            for (int im = 0; im < 4; im++) {
                int mr = warpM + im * 16 + gid;
                af[im][0] = __float_as_uint(As(buf, mr,     kb + tig));
                af[im][1] = __float_as_uint(As(buf, mr + 8, kb + tig));
                af[im][2] = __float_as_uint(As(buf, mr,     kb + tig + 4));
                af[im][3] = __float_as_uint(As(buf, mr + 8, kb + tig + 4));
            }
            uint32_t bf[4][2];
            #pragma unroll
            for (int jn = 0; jn < 4; jn++) {
                int nr = warpN + jn * 8 + gid;
                bf[jn][0] = __float_as_uint(Bs(buf, nr, kb + tig));
                bf[jn][1] = __float_as_uint(Bs(buf, nr, kb + tig + 4));
            }
            #pragma unroll
            for (int im = 0; im < 4; im++)
                #pragma unroll
                for (int jn = 0; jn < 4; jn++)
                    mma_tf32(acc[im][jn], af[im], bf[jn]);
        }
    };

    int nt = K / GBK;
    issue(0, 0);
    for (int i = 0; i < nt; i++) {
        if (i + 1 < nt) {
            issue(i + 1, (i + 1) & 1);
            asm volatile("cp.async.wait_group 1;\n");
        } else {
            asm volatile("cp.async.wait_group 0;\n");
        }
        __syncthreads();
        compute(i & 1);
        __syncthreads();
    }

    // Epilogue. m16n8 accumulator mapping:
    //   c0,c1 -> row gid,   cols 2*tig, 2*tig+1;  c2,c3 -> row gid+8
    #pragma unroll
    for (int im = 0; im < 4; im++) {
        #pragma unroll
        for (int jn = 0; jn < 4; jn++) {
            int col = n0 + warpN + jn * 8 + tig * 2;
            float b0v = bias[col], b1v = bias[col + 1];
            #pragma unroll
            for (int half = 0; half < 2; half++) {
                int row = m0 + warpM + im * 16 + gid + half * 8;
                float v0 = acc[im][jn][half * 2 + 0] + b0v;
                float v1 = acc[im][jn][half * 2 + 1] + b1v;
                if (EPI == EPI_GELU) {
                    v0 = 0.5f * v0 * (1.0f + erff(v0 * 0.70710678118654752f));
                    v1 = 0.5f * v1 * (1.0f + erff(v1 * 0.70710678118654752f));
                    // hbuf feeds ff2's A operand -> pre-round to tf32
                    v0 = round_tf32(v0);
                    v1 = round_tf32(v1);
                } else if (EPI == EPI_RES) {
                    float2 rr = *(const float2*)(res + (size_t)row * N + col);
                    v0 += rr.x; v1 += rr.y;
                }
                float2 o2; o2.x = v0; o2.y = v1;
                *(float2*)(C + (size_t)row * N + col) = o2;
            }
        }
    }
}

// ---------------------------------------------------------------------------
// Flash attention: one block per (b, h, 64-query tile). 256 threads.
// Output rounded to tf32 (feeds proj GEMM's A operand only).
// ---------------------------------------------------------------------------
#define FA_PAD 68
#define FA_SMEM (4 * 64 * FA_PAD * sizeof(float))   // 69632 B

__global__ __launch_bounds__(256)
void flash_kernel(const float* __restrict__ qkv, float* __restrict__ out)
{
    extern __shared__ float sm[];
    float* Qt = sm;
    float* Kt = sm + 64 * FA_PAD;
    float* Vs = sm + 2 * 64 * FA_PAD;
    float* Pt = sm + 3 * 64 * FA_PAD;

    int qt = gridDim.x - 1 - blockIdx.x;
    int h  = blockIdx.y;
    int b  = blockIdx.z;
    int t  = threadIdx.x;
    int tx = t & 15;
    int ty = t >> 4;

    const float* base = qkv + (size_t)b * SEQ * QKV_DIM;

    {
        int r  = t >> 2;
        int ds = (t & 3) << 4;
        const float* qrow = base + (size_t)(qt * 64 + r) * QKV_DIM + h * HDIM + ds;
        #pragma unroll
        for (int u = 0; u < 4; u++) {
            float4 v = ((const float4*)qrow)[u];
            int d = ds + u * 4;
            Qt[(d + 0) * FA_PAD + r] = v.x * 0.125f;
            Qt[(d + 1) * FA_PAD + r] = v.y * 0.125f;
            Qt[(d + 2) * FA_PAD + r] = v.z * 0.125f;
            Qt[(d + 3) * FA_PAD + r] = v.w * 0.125f;
        }
    }

    float m[4], l[4], o[4][4];
    #pragma unroll
    for (int i = 0; i < 4; i++) {
        m[i] = -1e30f; l[i] = 0.0f;
        #pragma unroll
        for (int j = 0; j < 4; j++) o[i][j] = 0.0f;
    }

    for (int kt = 0; kt <= qt; kt++) {
        __syncthreads();
        {
            int r  = t >> 2;
            int ds = (t & 3) << 4;
            const float* krow = base + (size_t)(kt * 64 + r) * QKV_DIM + DIM + h * HDIM + ds;
            const float* vrow = krow + DIM;
            #pragma unroll
            for (int u = 0; u < 4; u++) {
                float4 kv = ((const float4*)krow)[u];
                int d = ds + u * 4;
                Kt[(d + 0) * FA_PAD + r] = kv.x;
                Kt[(d + 1) * FA_PAD + r] = kv.y;
                Kt[(d + 2) * FA_PAD + r] = kv.z;
                Kt[(d + 3) * FA_PAD + r] = kv.w;
                ((float4*)(Vs + r * FA_PAD + ds))[u] = ((const float4*)vrow)[u];
            }
        }
        __syncthreads();

        float s[4][4];
        #pragma unroll
        for (int i = 0; i < 4; i++)
            #pragma unroll
            for (int j = 0; j < 4; j++) s[i][j] = 0.0f;

        #pragma unroll 8
        for (int d = 0; d < 64; d++) {
            float4 a4 = *(const float4*)(Qt + d * FA_PAD + ty * 4);
            float4 b4 = *(const float4*)(Kt + d * FA_PAD + tx * 4);
            float a[4] = {a4.x, a4.y, a4.z, a4.w};
            float bb[4] = {b4.x, b4.y, b4.z, b4.w};
            #pragma unroll
            for (int i = 0; i < 4; i++)
                #pragma unroll
                for (int j = 0; j < 4; j++)
                    s[i][j] += a[i] * bb[j];
        }

        if (kt == qt) {
            #pragma unroll
            for (int i = 0; i < 4; i++)
                #pragma unroll
                for (int j = 0; j < 4; j++)
                    if (tx * 4 + j > ty * 4 + i) s[i][j] = -1e30f;
        }

        #pragma unroll
        for (int i = 0; i < 4; i++) {
            float rm = fmaxf(fmaxf(s[i][0], s[i][1]), fmaxf(s[i][2], s[i][3]));
            #pragma unroll
            for (int w = 1; w < 16; w <<= 1)
                rm = fmaxf(rm, __shfl_xor_sync(0xffffffffu, rm, w));
            float mnew = fmaxf(m[i], rm);
            float alpha = __expf(m[i] - mnew);
            float rs = 0.0f;
            #pragma unroll
            for (int j = 0; j < 4; j++) {
                float p = __expf(s[i][j] - mnew);
                Pt[(tx * 4 + j) * FA_PAD + ty * 4 + i] = p;
                rs += p;
            }
            #pragma unroll
            for (int w = 1; w < 16; w <<= 1)
                rs += __shfl_xor_sync(0xffffffffu, rs, w);
            l[i] = l[i] * alpha + rs;
            m[i] = mnew;
            #pragma unroll
            for (int j = 0; j < 4; j++) o[i][j] *= alpha;
        }
        __syncthreads();

        #pragma unroll 8
        for (int k = 0; k < 64; k++) {
            float4 a4 = *(const float4*)(Pt + k * FA_PAD + ty * 4);
            float4 b4 = *(const float4*)(Vs + k * FA_PAD + tx * 4);
            float a[4] = {a4.x, a4.y, a4.z, a4.w};
            float bb[4] = {b4.x, b4.y, b4.z, b4.w};
            #pragma unroll
            for (int i = 0; i < 4; i++)
                #pragma unroll
                for (int j = 0; j < 4; j++)
                    o[i][j] += a[i] * bb[j];
        }
    }

    #pragma unroll
    for (int i = 0; i < 4; i++) {
        float inv = 1.0f / l[i];
        int row = qt * 64 + ty * 4 + i;
        float4 w4;
        w4.x = round_tf32(o[i][0] * inv);
        w4.y = round_tf32(o[i][1] * inv);
        w4.z = round_tf32(o[i][2] * inv);
        w4.w = round_tf32(o[i][3] * inv);
        *(float4*)(out + (size_t)(b * SEQ + row) * DIM + h * HDIM + tx * 4) = w4;
    }
}

// ---------------------------------------------------------------------------
// Launcher
// ---------------------------------------------------------------------------
extern "C" void kernel_launch(void* const* d_in, const int* in_sizes, int n_in,
                              void* d_out, int out_size)
{
    const float* x      = (const float*)d_in[0];
    const float* qkv_w  = (const float*)d_in[1];
    const float* qkv_b  = (const float*)d_in[2];
    const float* proj_w = (const float*)d_in[3];
    const float* proj_b = (const float*)d_in[4];
    const float* ff1_w  = (const float*)d_in[5];
    const float* ff1_b  = (const float*)d_in[6];
    const float* ff2_w  = (const float*)d_in[7];
    const float* ff2_b  = (const float*)d_in[8];
    const float* ln1_g  = (const float*)d_in[9];
    const float* ln1_b  = (const float*)d_in[10];
    const float* ln2_g  = (const float*)d_in[11];
    const float* ln2_b  = (const float*)d_in[12];
    float* out = (float*)d_out;

    float *xn, *qkv, *att, *x1, *hbuf, *wq, *wp, *w1, *w2;
    cudaGetSymbolAddress((void**)&xn,   g_xn);
    cudaGetSymbolAddress((void**)&qkv,  g_qkv);
    cudaGetSymbolAddress((void**)&att,  g_att);
    cudaGetSymbolAddress((void**)&x1,   g_x1);
    cudaGetSymbolAddress((void**)&hbuf, g_h);
    cudaGetSymbolAddress((void**)&wq,   g_wq);
    cudaGetSymbolAddress((void**)&wp,   g_wp);
    cudaGetSymbolAddress((void**)&w1,   g_w1);
    cudaGetSymbolAddress((void**)&w2,   g_w2);

    cudaFuncSetAttribute(flash_kernel,
                         cudaFuncAttributeMaxDynamicSharedMemorySize, FA_SMEM);
    cudaFuncSetAttribute(gemm_tc_kernel<EPI_BIAS>,
                         cudaFuncAttributeMaxDynamicSharedMemorySize, GEMM_SMEM);
    cudaFuncSetAttribute(gemm_tc_kernel<EPI_GELU>,
                         cudaFuncAttributeMaxDynamicSharedMemorySize, GEMM_SMEM);
    cudaFuncSetAttribute(gemm_tc_kernel<EPI_RES>,
                         cudaFuncAttributeMaxDynamicSharedMemorySize, GEMM_SMEM);

    // 0. Pre-round weights to tf32 (idempotent, deterministic)
    round_kernel<<<(QKV_DIM * DIM / 4 + 255) / 256, 256>>>(qkv_w, wq, QKV_DIM * DIM);
    round_kernel<<<(DIM * DIM / 4 + 255) / 256, 256>>>(proj_w, wp, DIM * DIM);
    round_kernel<<<(HIDDEN * DIM / 4 + 255) / 256, 256>>>(ff1_w, w1, HIDDEN * DIM);
    round_kernel<<<(DIM * HIDDEN / 4 + 255) / 256, 256>>>(ff2_w, w2, DIM * HIDDEN);

    // 1. LN1 (output tf32-rounded)
    ln_kernel<<<TOKENS, 256>>>(x, ln1_g, ln1_b, xn);

    // 2. QKV projection
    {
        dim3 grid(QKV_DIM / 128, TOKENS / 128);
        gemm_tc_kernel<EPI_BIAS><<<grid, 256, GEMM_SMEM>>>(xn, wq, qkv_b, nullptr, qkv,
                                                           TOKENS, QKV_DIM, DIM);
    }

    // 3. Flash causal attention (output tf32-rounded)
    {
        dim3 grid(SEQ / 64, NHEAD, BATCH);
        flash_kernel<<<grid, 256, FA_SMEM>>>(qkv, att);
    }

    // 4. proj + residual
    {
        dim3 grid(DIM / 128, TOKENS / 128);
        gemm_tc_kernel<EPI_RES><<<grid, 256, GEMM_SMEM>>>(att, wp, proj_b, x, x1,
                                                          TOKENS, DIM, DIM);
    }

    // 5. LN2 (output tf32-rounded)
    ln_kernel<<<TOKENS, 256>>>(x1, ln2_g, ln2_b, xn);

    // 6. FF1 + GELU (output tf32-rounded)
    {
        dim3 grid(HIDDEN / 128, TOKENS / 128);
        gemm_tc_kernel<EPI_GELU><<<grid, 256, GEMM_SMEM>>>(xn, w1, ff1_b, nullptr, hbuf,
                                                           TOKENS, HIDDEN, DIM);
    }

    // 7. FF2 + residual into d_out
    {
        dim3 grid(DIM / 128, TOKENS / 128);
        gemm_tc_kernel<EPI_RES><<<grid, 256, GEMM_SMEM>>>(hbuf, w2, ff2_b, x1, out,
                                                          TOKENS, DIM, HIDDEN);
    }
}

// round 8
// speedup vs baseline: 6.6557x; 1.4524x over previous
#include <cuda_runtime.h>
#include <cuda_bf16.h>
#include <math.h>
#include <stdint.h>

// ---------------------------------------------------------------------------
// Problem constants
// ---------------------------------------------------------------------------
#define BATCH    2
#define SEQ      2048
#define DIM      1024
#define NHEAD    16
#define HDIM     64
#define HIDDEN   4096
#define TOKENS   (BATCH * SEQ)          // 4096
#define QKV_DIM  (3 * DIM)              // 3072
#define LN_EPS   1e-5f

// ---------------------------------------------------------------------------
// Scratch buffers
// ---------------------------------------------------------------------------
__device__ float g_xn [TOKENS * DIM];
__device__ float g_qkv[TOKENS * QKV_DIM];
__device__ float g_att[TOKENS * DIM];
__device__ float g_x1 [TOKENS * DIM];
__device__ float g_h  [TOKENS * HIDDEN];
// tf32-pre-rounded weights
__device__ float g_wq[QKV_DIM * DIM];
__device__ float g_wp[DIM * DIM];
__device__ float g_w1[HIDDEN * DIM];
__device__ float g_w2[DIM * HIDDEN];

__device__ __forceinline__ uint32_t f2tf32(float x)
{
    uint32_t r;
    asm("cvt.rna.tf32.f32 %0, %1;" : "=r"(r) : "f"(x));
    return r;
}
__device__ __forceinline__ float round_tf32(float x)
{
    return __uint_as_float(f2tf32(x));
}

// ---------------------------------------------------------------------------
// Weight pre-rounding
// ---------------------------------------------------------------------------
__global__ void round_kernel(const float* __restrict__ in,
                             float* __restrict__ out, int n)
{
    int i = (blockIdx.x * 256 + threadIdx.x) * 4;
    if (i < n) {
        float4 v = *(const float4*)(in + i);
        v.x = round_tf32(v.x); v.y = round_tf32(v.y);
        v.z = round_tf32(v.z); v.w = round_tf32(v.w);
        *(float4*)(out + i) = v;
    }
}

// ---------------------------------------------------------------------------
// LayerNorm (output rounded to tf32)
// ---------------------------------------------------------------------------
__global__ void ln_kernel(const float* __restrict__ in,
                          const float* __restrict__ gamma,
                          const float* __restrict__ beta,
                          float* __restrict__ out)
{
    int row = blockIdx.x;
    int tid = threadIdx.x;               // 256
    const float4* rp = (const float4*)(in + (size_t)row * DIM);
    float4 v = rp[tid];

    float s  = v.x + v.y + v.z + v.w;
    float s2 = v.x*v.x + v.y*v.y + v.z*v.z + v.w*v.w;

    __shared__ float rs[256];
    __shared__ float rq[256];
    rs[tid] = s; rq[tid] = s2;
    __syncthreads();
    #pragma unroll
    for (int o = 128; o > 0; o >>= 1) {
        if (tid < o) { rs[tid] += rs[tid + o]; rq[tid] += rq[tid + o]; }
        __syncthreads();
    }
    float mu  = rs[0] * (1.0f / DIM);
    float var = rq[0] * (1.0f / DIM) - mu * mu;
    float rstd = rsqrtf(var + LN_EPS);

    float4 g4 = ((const float4*)gamma)[tid];
    float4 b4 = ((const float4*)beta)[tid];
    float4 o4;
    o4.x = round_tf32((v.x - mu) * rstd * g4.x + b4.x);
    o4.y = round_tf32((v.y - mu) * rstd * g4.y + b4.y);
    o4.z = round_tf32((v.z - mu) * rstd * g4.z + b4.z);
    o4.w = round_tf32((v.w - mu) * rstd * g4.w + b4.w);
    ((float4*)(out + (size_t)row * DIM))[tid] = o4;
}

// ---------------------------------------------------------------------------
// TF32 tensor-core GEMM, cp.async double-buffered, dynamic smem.
// ---------------------------------------------------------------------------
#define EPI_BIAS     0
#define EPI_GELU     1
#define EPI_RES      2
#define EPI_BIAS_RND 3   // bias + tf32-round output (for qkv -> attention)
#define GBK   32
#define GPAD  36
#define GEMM_SMEM (2 * 2 * 128 * GPAD * sizeof(float))   // 73728 B

__device__ __forceinline__ void mma_tf32(float c[4],
                                         const uint32_t a[4],
                                         const uint32_t b[2])
{
    asm volatile(
        "mma.sync.aligned.m16n8k8.row.col.f32.tf32.tf32.f32 "
        "{%0,%1,%2,%3}, {%4,%5,%6,%7}, {%8,%9}, {%0,%1,%2,%3};"
        : "+f"(c[0]), "+f"(c[1]), "+f"(c[2]), "+f"(c[3])
        : "r"(a[0]), "r"(a[1]), "r"(a[2]), "r"(a[3]),
          "r"(b[0]), "r"(b[1]));
}

template<int EPI>
__global__ __launch_bounds__(256, 2)
void gemm_tc_kernel(const float* __restrict__ A,
                    const float* __restrict__ W,
                    const float* __restrict__ bias,
                    const float* __restrict__ res,
                    float* __restrict__ C,
                    int M, int N, int K)
{
    extern __shared__ float smem_g[];
    float* AsBase = smem_g;
    float* BsBase = smem_g + 2 * 128 * GPAD;
    auto As = [&](int buf, int r, int c) -> float& {
        return AsBase[(buf * 128 + r) * GPAD + c];
    };
    auto Bs = [&](int buf, int r, int c) -> float& {
        return BsBase[(buf * 128 + r) * GPAD + c];
    };

    int t    = threadIdx.x;
    int lane = t & 31;
    int wid  = t >> 5;
    int gid  = lane >> 2;
    int tig  = lane & 3;
    int warpM = (wid >> 2) * 64;
    int warpN = (wid & 3) * 32;
    int m0 = blockIdx.y * 128;
    int n0 = blockIdx.x * 128;

    int lrow = t >> 3;
    int lkc  = (t & 7) << 2;

    float acc[4][4][4];
    #pragma unroll
    for (int im = 0; im < 4; im++)
        #pragma unroll
        for (int jn = 0; jn < 4; jn++)
            #pragma unroll
            for (int r = 0; r < 4; r++) acc[im][jn][r] = 0.0f;

    const float* agbase = A + (size_t)(m0 + lrow) * K + lkc;
    const float* bgbase = W + (size_t)(n0 + lrow) * K + lkc;

    auto issue = [&](int kt, int buf) {
        const float* ag = agbase + kt * GBK;
        const float* bg = bgbase + kt * GBK;
        #pragma unroll
        for (int p = 0; p < 4; p++) {
            uint32_t da = (uint32_t)__cvta_generic_to_shared(&As(buf, lrow + p * 32, lkc));
            asm volatile("cp.async.cg.shared.global [%0], [%1], 16;\n"
                         :: "r"(da), "l"(ag + (size_t)p * 32 * K));
            uint32_t db = (uint32_t)__cvta_generic_to_shared(&Bs(buf, lrow + p * 32, lkc));
            asm volatile("cp.async.cg.shared.global [%0], [%1], 16;\n"
                         :: "r"(db), "l"(bg + (size_t)p * 32 * K));
        }
        asm volatile("cp.async.commit_group;\n");
    };

    auto compute = [&](int buf) {
        #pragma unroll
        for (int kb = 0; kb < GBK; kb += 8) {
            uint32_t af[4][4];
            #pragma unroll
            for (int im = 0; im < 4; im++) {
                int mr = warpM + im * 16 + gid;
                af[im][0] = __float_as_uint(As(buf, mr,     kb + tig));
                af[im][1] = __float_as_uint(As(buf, mr + 8, kb + tig));
                af[im][2] = __float_as_uint(As(buf, mr,     kb + tig + 4));
                af[im][3] = __float_as_uint(As(buf, mr + 8, kb + tig + 4));
            }
            uint32_t bf[4][2];
            #pragma unroll
            for (int jn = 0; jn < 4; jn++) {
                int nr = warpN + jn * 8 + gid;
                bf[jn][0] = __float_as_uint(Bs(buf, nr, kb + tig));
                bf[jn][1] = __float_as_uint(Bs(buf, nr, kb + tig + 4));
            }
            #pragma unroll
            for (int im = 0; im < 4; im++)
                #pragma unroll
                for (int jn = 0; jn < 4; jn++)
                    mma_tf32(acc[im][jn], af[im], bf[jn]);
        }
    };

    int nt = K / GBK;
    issue(0, 0);
    for (int i = 0; i < nt; i++) {
        if (i + 1 < nt) {
            issue(i + 1, (i + 1) & 1);
            asm volatile("cp.async.wait_group 1;\n");
        } else {
            asm volatile("cp.async.wait_group 0;\n");
        }
        __syncthreads();
        compute(i & 1);
        __syncthreads();
    }

    #pragma unroll
    for (int im = 0; im < 4; im++) {
        #pragma unroll
        for (int jn = 0; jn < 4; jn++) {
            int col = n0 + warpN + jn * 8 + tig * 2;
            float b0v = bias[col], b1v = bias[col + 1];
            #pragma unroll
            for (int half = 0; half < 2; half++) {
                int row = m0 + warpM + im * 16 + gid + half * 8;
                float v0 = acc[im][jn][half * 2 + 0] + b0v;
                float v1 = acc[im][jn][half * 2 + 1] + b1v;
                if (EPI == EPI_GELU) {
                    v0 = 0.5f * v0 * (1.0f + erff(v0 * 0.70710678118654752f));
                    v1 = 0.5f * v1 * (1.0f + erff(v1 * 0.70710678118654752f));
                    v0 = round_tf32(v0);
                    v1 = round_tf32(v1);
                } else if (EPI == EPI_RES) {
                    float2 rr = *(const float2*)(res + (size_t)row * N + col);
                    v0 += rr.x; v1 += rr.y;
                } else if (EPI == EPI_BIAS_RND) {
                    v0 = round_tf32(v0);
                    v1 = round_tf32(v1);
                }
                float2 o2; o2.x = v0; o2.y = v1;
                *(float2*)(C + (size_t)row * N + col) = o2;
            }
        }
    }
}

// ---------------------------------------------------------------------------
// Tensor-core flash attention.
//   One block per (b, h, 128-query tile). 256 threads = 8 warps x 16 q rows.
//   k-tiles of 64. qkv values are already tf32-rounded (EPI_BIAS_RND).
//   S = QK^T and O += PV both via m16n8k8 tf32 MMA. Softmax in registers.
// Smem: Qs[128][68] (q-major), Ks[64][68] (key-major), Vt[64][68] (d-major),
//       Ps[128][68] (q-major, warp-private rows).
// ---------------------------------------------------------------------------
#define FPAD 68
#define FTC_SMEM ((128 + 64 + 64 + 128) * FPAD * sizeof(float))   // 104448 B

__global__ __launch_bounds__(256, 2)
void flash_tc_kernel(const float* __restrict__ qkv, float* __restrict__ out)
{
    extern __shared__ float sm[];
    float* Qs = sm;                         // [128][FPAD]
    float* Ks = Qs + 128 * FPAD;            // [64][FPAD]
    float* Vt = Ks + 64 * FPAD;             // [64][FPAD]
    float* Ps = Vt + 64 * FPAD;             // [128][FPAD]

    int QT = gridDim.x - 1 - blockIdx.x;    // longest tiles first
    int h  = blockIdx.y;
    int b  = blockIdx.z;
    int t  = threadIdx.x;
    int lane = t & 31;
    int wid  = t >> 5;
    int gid  = lane >> 2;
    int tig  = lane & 3;
    int warpRow = wid * 16;

    const float* base = qkv + (size_t)b * SEQ * QKV_DIM;

    // ---- load Q tile (128 x 64), scale by 0.125 (exact, preserves tf32) ----
    {
        int r  = t >> 1;                    // 0..127
        int d0 = (t & 1) * 32;
        const float* qrow = base + (size_t)(QT * 128 + r) * QKV_DIM + h * HDIM + d0;
        float* dst = Qs + r * FPAD + d0;
        #pragma unroll
        for (int u = 0; u < 8; u++) {
            float4 v = ((const float4*)qrow)[u];
            v.x *= 0.125f; v.y *= 0.125f; v.z *= 0.125f; v.w *= 0.125f;
            ((float4*)dst)[u] = v;
        }
    }

    float m0 = -1e30f, m1 = -1e30f, l0 = 0.0f, l1 = 0.0f;
    float oacc[8][4];
    #pragma unroll
    for (int dn = 0; dn < 8; dn++)
        #pragma unroll
        for (int r = 0; r < 4; r++) oacc[dn][r] = 0.0f;

    int q0 = QT * 128 + warpRow + gid;      // this thread's first q row
    int ktmax = QT * 2 + 1;

    for (int kt = 0; kt <= ktmax; kt++) {
        __syncthreads();                    // prior Ks/Vt consumers done
        // ---- load K tile (64x64, key-major) and V tile (transposed) ----
        {
            int r  = t >> 2;                // 0..63
            int c0 = (t & 3) * 16;
            const float* krow = base + (size_t)(kt * 64 + r) * QKV_DIM + DIM + h * HDIM + c0;
            float* kdst = Ks + r * FPAD + c0;
            #pragma unroll
            for (int u = 0; u < 4; u++)
                ((float4*)kdst)[u] = ((const float4*)krow)[u];

            int j  = t & 63;
            int d0 = (t >> 6) * 16;
            const float* vrow = base + (size_t)(kt * 64 + j) * QKV_DIM + 2 * DIM + h * HDIM + d0;
            #pragma unroll
            for (int u = 0; u < 4; u++) {
                float4 v = ((const float4*)vrow)[u];
                int d = d0 + u * 4;
                Vt[(d + 0) * FPAD + j] = v.x;
                Vt[(d + 1) * FPAD + j] = v.y;
                Vt[(d + 2) * FPAD + j] = v.z;
                Vt[(d + 3) * FPAD + j] = v.w;
            }
        }
        __syncthreads();

        // ---- S = Q K^T : warp computes 16 x 64 ----
        float sacc[8][4];
        #pragma unroll
        for (int jn = 0; jn < 8; jn++)
            #pragma unroll
            for (int r = 0; r < 4; r++) sacc[jn][r] = 0.0f;

        #pragma unroll
        for (int kb = 0; kb < 64; kb += 8) {
            uint32_t af[4];
            af[0] = __float_as_uint(Qs[(warpRow + gid    ) * FPAD + kb + tig]);
            af[1] = __float_as_uint(Qs[(warpRow + gid + 8) * FPAD + kb + tig]);
            af[2] = __float_as_uint(Qs[(warpRow + gid    ) * FPAD + kb + tig + 4]);
            af[3] = __float_as_uint(Qs[(warpRow + gid + 8) * FPAD + kb + tig + 4]);
            #pragma unroll
            for (int jn = 0; jn < 8; jn++) {
                uint32_t bf[2];
                bf[0] = __float_as_uint(Ks[(jn * 8 + gid) * FPAD + kb + tig]);
                bf[1] = __float_as_uint(Ks[(jn * 8 + gid) * FPAD + kb + tig + 4]);
                mma_tf32(sacc[jn], af, bf);
            }
        }

        // ---- causal mask (only tiles that can straddle the diagonal) ----
        if (kt * 64 + 63 > QT * 128 + warpRow) {
            #pragma unroll
            for (int jn = 0; jn < 8; jn++) {
                int jg = kt * 64 + jn * 8 + tig * 2;
                if (jg     > q0    ) sacc[jn][0] = -1e30f;
                if (jg + 1 > q0    ) sacc[jn][1] = -1e30f;
                if (jg     > q0 + 8) sacc[jn][2] = -1e30f;
                if (jg + 1 > q0 + 8) sacc[jn][3] = -1e30f;
            }
        }

        // ---- online softmax (rows gid and gid+8 of this warp tile) ----
        float rm0 = -1e30f, rm1 = -1e30f;
        #pragma unroll
        for (int jn = 0; jn < 8; jn++) {
            rm0 = fmaxf(rm0, fmaxf(sacc[jn][0], sacc[jn][1]));
            rm1 = fmaxf(rm1, fmaxf(sacc[jn][2], sacc[jn][3]));
        }
        rm0 = fmaxf(rm0, __shfl_xor_sync(0xffffffffu, rm0, 1));
        rm0 = fmaxf(rm0, __shfl_xor_sync(0xffffffffu, rm0, 2));
        rm1 = fmaxf(rm1, __shfl_xor_sync(0xffffffffu, rm1, 1));
        rm1 = fmaxf(rm1, __shfl_xor_sync(0xffffffffu, rm1, 2));

        float mn0 = fmaxf(m0, rm0);
        float mn1 = fmaxf(m1, rm1);
        float a0 = __expf(m0 - mn0);
        float a1 = __expf(m1 - mn1);

        float rs0 = 0.0f, rs1 = 0.0f;
        #pragma unroll
        for (int jn = 0; jn < 8; jn++) {
            float p0 = __expf(sacc[jn][0] - mn0);
            float p1 = __expf(sacc[jn][1] - mn0);
            float p2 = __expf(sacc[jn][2] - mn1);
            float p3 = __expf(sacc[jn][3] - mn1);
            rs0 += p0 + p1;
            rs1 += p2 + p3;
            int col = jn * 8 + tig * 2;
            float2 w0; w0.x = round_tf32(p0); w0.y = round_tf32(p1);
            float2 w1; w1.x = round_tf32(p2); w1.y = round_tf32(p3);
            *(float2*)(Ps + (warpRow + gid    ) * FPAD + col) = w0;
            *(float2*)(Ps + (warpRow + gid + 8) * FPAD + col) = w1;
        }
        rs0 += __shfl_xor_sync(0xffffffffu, rs0, 1);
        rs0 += __shfl_xor_sync(0xffffffffu, rs0, 2);
        rs1 += __shfl_xor_sync(0xffffffffu, rs1, 1);
        rs1 += __shfl_xor_sync(0xffffffffu, rs1, 2);

        l0 = l0 * a0 + rs0; m0 = mn0;
        l1 = l1 * a1 + rs1; m1 = mn1;
        #pragma unroll
        for (int dn = 0; dn < 8; dn++) {
            oacc[dn][0] *= a0; oacc[dn][1] *= a0;
            oacc[dn][2] *= a1; oacc[dn][3] *= a1;
        }
        __syncwarp();    // Ps visible within warp

        // ---- O += P V : warp computes 16 x 64 ----
        #pragma unroll
        for (int kb = 0; kb < 64; kb += 8) {
            uint32_t af[4];
            af[0] = __float_as_uint(Ps[(warpRow + gid    ) * FPAD + kb + tig]);
            af[1] = __float_as_uint(Ps[(warpRow + gid + 8) * FPAD + kb + tig]);
            af[2] = __float_as_uint(Ps[(warpRow + gid    ) * FPAD + kb + tig + 4]);
            af[3] = __float_as_uint(Ps[(warpRow + gid + 8) * FPAD + kb + tig + 4]);
            #pragma unroll
            for (int dn = 0; dn < 8; dn++) {
                uint32_t bf[2];
                bf[0] = __float_as_uint(Vt[(dn * 8 + gid) * FPAD + kb + tig]);
                bf[1] = __float_as_uint(Vt[(dn * 8 + gid) * FPAD + kb + tig + 4]);
                mma_tf32(oacc[dn], af, bf);
            }
        }
        __syncwarp();    // Ps reads done before next iteration overwrites
    }

    // ---- epilogue: normalize, round to tf32 (feeds proj GEMM), store ----
    float inv0 = 1.0f / l0;
    float inv1 = 1.0f / l1;
    float* orow0 = out + ((size_t)(b * SEQ) + q0    ) * DIM + h * HDIM;
    float* orow1 = out + ((size_t)(b * SEQ) + q0 + 8) * DIM + h * HDIM;
    #pragma unroll
    for (int dn = 0; dn < 8; dn++) {
        int col = dn * 8 + tig * 2;
        float2 w0; w0.x = round_tf32(oacc[dn][0] * inv0);
                   w0.y = round_tf32(oacc[dn][1] * inv0);
        float2 w1; w1.x = round_tf32(oacc[dn][2] * inv1);
                   w1.y = round_tf32(oacc[dn][3] * inv1);
        *(float2*)(orow0 + col) = w0;
        *(float2*)(orow1 + col) = w1;
    }
}

// ---------------------------------------------------------------------------
// Launcher
// ---------------------------------------------------------------------------
extern "C" void kernel_launch(void* const* d_in, const int* in_sizes, int n_in,
                              void* d_out, int out_size)
{
    const float* x      = (const float*)d_in[0];
    const float* qkv_w  = (const float*)d_in[1];
    const float* qkv_b  = (const float*)d_in[2];
    const float* proj_w = (const float*)d_in[3];
    const float* proj_b = (const float*)d_in[4];
    const float* ff1_w  = (const float*)d_in[5];
    const float* ff1_b  = (const float*)d_in[6];
    const float* ff2_w  = (const float*)d_in[7];
    const float* ff2_b  = (const float*)d_in[8];
    const float* ln1_g  = (const float*)d_in[9];
    const float* ln1_b  = (const float*)d_in[10];
    const float* ln2_g  = (const float*)d_in[11];
    const float* ln2_b  = (const float*)d_in[12];
    float* out = (float*)d_out;

    float *xn, *qkv, *att, *x1, *hbuf, *wq, *wp, *w1, *w2;
    cudaGetSymbolAddress((void**)&xn,   g_xn);
    cudaGetSymbolAddress((void**)&qkv,  g_qkv);
    cudaGetSymbolAddress((void**)&att,  g_att);
    cudaGetSymbolAddress((void**)&x1,   g_x1);
    cudaGetSymbolAddress((void**)&hbuf, g_h);
    cudaGetSymbolAddress((void**)&wq,   g_wq);
    cudaGetSymbolAddress((void**)&wp,   g_wp);
    cudaGetSymbolAddress((void**)&w1,   g_w1);
    cudaGetSymbolAddress((void**)&w2,   g_w2);

    cudaFuncSetAttribute(flash_tc_kernel,
                         cudaFuncAttributeMaxDynamicSharedMemorySize, FTC_SMEM);
    cudaFuncSetAttribute(gemm_tc_kernel<EPI_BIAS_RND>,
                         cudaFuncAttributeMaxDynamicSharedMemorySize, GEMM_SMEM);
    cudaFuncSetAttribute(gemm_tc_kernel<EPI_GELU>,
                         cudaFuncAttributeMaxDynamicSharedMemorySize, GEMM_SMEM);
    cudaFuncSetAttribute(gemm_tc_kernel<EPI_RES>,
                         cudaFuncAttributeMaxDynamicSharedMemorySize, GEMM_SMEM);

    // 0. Pre-round weights to tf32
    round_kernel<<<(QKV_DIM * DIM / 4 + 255) / 256, 256>>>(qkv_w, wq, QKV_DIM * DIM);
    round_kernel<<<(DIM * DIM / 4 + 255) / 256, 256>>>(proj_w, wp, DIM * DIM);
    round_kernel<<<(HIDDEN * DIM / 4 + 255) / 256, 256>>>(ff1_w, w1, HIDDEN * DIM);
    round_kernel<<<(DIM * HIDDEN / 4 + 255) / 256, 256>>>(ff2_w, w2, DIM * HIDDEN);

    // 1. LN1
    ln_kernel<<<TOKENS, 256>>>(x, ln1_g, ln1_b, xn);

    // 2. QKV projection (output tf32-rounded: feeds attention only)
    {
        dim3 grid(QKV_DIM / 128, TOKENS / 128);
        gemm_tc_kernel<EPI_BIAS_RND><<<grid, 256, GEMM_SMEM>>>(xn, wq, qkv_b, nullptr, qkv,
                                                               TOKENS, QKV_DIM, DIM);
    }

    // 3. Tensor-core flash attention
    {
        dim3 grid(SEQ / 128, NHEAD, BATCH);
        flash_tc_kernel<<<grid, 256, FTC_SMEM>>>(qkv, att);
    }

    // 4. proj + residual
    {
        dim3 grid(DIM / 128, TOKENS / 128);
        gemm_tc_kernel<EPI_RES><<<grid, 256, GEMM_SMEM>>>(att, wp, proj_b, x, x1,
                                                          TOKENS, DIM, DIM);
    }

    // 5. LN2
    ln_kernel<<<TOKENS, 256>>>(x1, ln2_g, ln2_b, xn);

    // 6. FF1 + GELU
    {
        dim3 grid(HIDDEN / 128, TOKENS / 128);
        gemm_tc_kernel<EPI_GELU><<<grid, 256, GEMM_SMEM>>>(xn, w1, ff1_b, nullptr, hbuf,
                                                           TOKENS, HIDDEN, DIM);
    }

    // 7. FF2 + residual into d_out
    {
        dim3 grid(DIM / 128, TOKENS / 128);
        gemm_tc_kernel<EPI_RES><<<grid, 256, GEMM_SMEM>>>(hbuf, w2, ff2_b, x1, out,
                                                          TOKENS, DIM, HIDDEN);
    }
}

// round 11
// speedup vs baseline: 11.9965x; 1.8024x over previous
#include <cuda_runtime.h>
#include <cuda_bf16.h>
#include <math.h>
#include <stdint.h>

// ---------------------------------------------------------------------------
// Problem constants
// ---------------------------------------------------------------------------
#define BATCH    2
#define SEQ      2048
#define DIM      1024
#define NHEAD    16
#define HDIM     64
#define HIDDEN   4096
#define TOKENS   (BATCH * SEQ)          // 4096
#define QKV_DIM  (3 * DIM)              // 3072
#define LN_EPS   1e-5f

// ---------------------------------------------------------------------------
// Scratch buffers (bf16 activations where they only feed tensor ops;
// residual stream fp32)
// ---------------------------------------------------------------------------
__device__ __nv_bfloat16 g_xn [TOKENS * DIM];
__device__ __nv_bfloat16 g_qkv[TOKENS * QKV_DIM];
__device__ __nv_bfloat16 g_att[TOKENS * DIM];
__device__ float         g_x1 [TOKENS * DIM];
__device__ __nv_bfloat16 g_h  [TOKENS * HIDDEN];
// bf16 weights
__device__ __nv_bfloat16 g_wq[QKV_DIM * DIM];
__device__ __nv_bfloat16 g_wp[DIM * DIM];
__device__ __nv_bfloat16 g_w1[HIDDEN * DIM];
__device__ __nv_bfloat16 g_w2[DIM * HIDDEN];

// ---------------------------------------------------------------------------
// Helpers
// ---------------------------------------------------------------------------
__device__ __forceinline__ uint32_t smem_u32(const void* p)
{
    return (uint32_t)__cvta_generic_to_shared(p);
}

__device__ __forceinline__ void mma_bf16(float c[4], const uint32_t a[4],
                                         uint32_t b0, uint32_t b1)
{
    asm volatile(
        "mma.sync.aligned.m16n8k16.row.col.f32.bf16.bf16.f32 "
        "{%0,%1,%2,%3}, {%4,%5,%6,%7}, {%8,%9}, {%0,%1,%2,%3};"
        : "+f"(c[0]), "+f"(c[1]), "+f"(c[2]), "+f"(c[3])
        : "r"(a[0]), "r"(a[1]), "r"(a[2]), "r"(a[3]), "r"(b0), "r"(b1));
}

// ---------------------------------------------------------------------------
// Weight conversion fp32 -> bf16
// ---------------------------------------------------------------------------
__global__ void cvt_bf16_kernel(const float* __restrict__ in,
                                __nv_bfloat16* __restrict__ out, int n)
{
    int i = (blockIdx.x * 256 + threadIdx.x) * 4;
    if (i < n) {
        float4 v = *(const float4*)(in + i);
        __nv_bfloat162 lo = __floats2bfloat162_rn(v.x, v.y);
        __nv_bfloat162 hi = __floats2bfloat162_rn(v.z, v.w);
        uint2 pk;
        pk.x = *(uint32_t*)&lo;
        pk.y = *(uint32_t*)&hi;
        *(uint2*)(out + i) = pk;
    }
}

// ---------------------------------------------------------------------------
// LayerNorm: fp32 in, bf16 out
// ---------------------------------------------------------------------------
__global__ void ln_kernel(const float* __restrict__ in,
                          const float* __restrict__ gamma,
                          const float* __restrict__ beta,
                          __nv_bfloat16* __restrict__ out)
{
    int row = blockIdx.x;
    int tid = threadIdx.x;               // 256
    const float4* rp = (const float4*)(in + (size_t)row * DIM);
    float4 v = rp[tid];

    float s  = v.x + v.y + v.z + v.w;
    float s2 = v.x*v.x + v.y*v.y + v.z*v.z + v.w*v.w;

    __shared__ float rs[256];
    __shared__ float rq[256];
    rs[tid] = s; rq[tid] = s2;
    __syncthreads();
    #pragma unroll
    for (int o = 128; o > 0; o >>= 1) {
        if (tid < o) { rs[tid] += rs[tid + o]; rq[tid] += rq[tid + o]; }
        __syncthreads();
    }
    float mu  = rs[0] * (1.0f / DIM);
    float var = rq[0] * (1.0f / DIM) - mu * mu;
    float rstd = rsqrtf(var + LN_EPS);

    float4 g4 = ((const float4*)gamma)[tid];
    float4 b4 = ((const float4*)beta)[tid];
    __nv_bfloat162 lo = __floats2bfloat162_rn(
        (v.x - mu) * rstd * g4.x + b4.x, (v.y - mu) * rstd * g4.y + b4.y);
    __nv_bfloat162 hi = __floats2bfloat162_rn(
        (v.z - mu) * rstd * g4.z + b4.z, (v.w - mu) * rstd * g4.w + b4.w);
    uint2 pk;
    pk.x = *(uint32_t*)&lo;
    pk.y = *(uint32_t*)&hi;
    *(uint2*)(out + (size_t)row * DIM + tid * 4) = pk;
}

// ---------------------------------------------------------------------------
// BF16 tensor-core GEMM, cp.async double-buffered, SCALAR fragment loads
// (no ldmatrix — mirrors the access pattern proven on this part in tf32).
//   C[M,N] = A[M,K] @ W[N,K]^T + bias (+ epilogue)
//   BM=BN=128, BK=64 bf16, 2 stages. 8 warps, warp tile 64x32, m16n8k16.
// m16n8k16 fragment map (thread = gid*4+tig):
//   a0=(gid, 2t..2t+1) a1=(gid+8, ..) a2=(gid, 2t+8..) a3=(gid+8, 2t+8..)
//   b0=(n=gid, k=2t..2t+1) b1=(n=gid, k=2t+8..2t+9)
//   c0,c1=(gid, 2t,2t+1) c2,c3=(gid+8, ..)
// ---------------------------------------------------------------------------
#define EPI_BIAS 0   // bias, bf16 out (qkv)
#define EPI_GELU 1   // bias+gelu, bf16 out (ff1)
#define EPI_RES  2   // bias+residual, fp32 out (proj, ff2)
#define GBK   64
#define SPAD  72     // row stride in bf16 elems (64 + 8 pad, 144 B)
#define GEMM_SMEM (2 * 2 * 128 * SPAD * sizeof(uint16_t))   // 73728 B

template<int EPI>
__global__ __launch_bounds__(256, 2)
void gemm_bf16_kernel(const __nv_bfloat16* __restrict__ A,
                      const __nv_bfloat16* __restrict__ W,
                      const float* __restrict__ bias,
                      const float* __restrict__ res,
                      void* __restrict__ Cv,
                      int M, int N, int K)
{
    extern __shared__ __align__(16) uint16_t smem_b[];
    uint16_t* AsB = smem_b;                      // [2][128][SPAD]
    uint16_t* BsB = smem_b + 2 * 128 * SPAD;

    int t    = threadIdx.x;
    int lane = t & 31;
    int wid  = t >> 5;
    int gid  = lane >> 2;
    int tig  = lane & 3;
    int warpM = (wid >> 2) * 64;
    int warpN = (wid & 3) * 32;
    int m0 = blockIdx.y * 128;
    int n0 = blockIdx.x * 128;

    int lrow = t >> 3;            // 0..31
    int lk   = (t & 7) * 8;       // bf16 idx 0..56

    float acc[4][4][4];
    #pragma unroll
    for (int im = 0; im < 4; im++)
        #pragma unroll
        for (int jn = 0; jn < 4; jn++)
            #pragma unroll
            for (int r = 0; r < 4; r++) acc[im][jn][r] = 0.0f;

    const __nv_bfloat16* agbase = A + (size_t)(m0 + lrow) * K + lk;
    const __nv_bfloat16* bgbase = W + (size_t)(n0 + lrow) * K + lk;

    auto issue = [&](int kt, int buf) {
        const __nv_bfloat16* ag = agbase + kt * GBK;
        const __nv_bfloat16* bg = bgbase + kt * GBK;
        uint16_t* Asp = AsB + buf * 128 * SPAD;
        uint16_t* Bsp = BsB + buf * 128 * SPAD;
        #pragma unroll
        for (int p = 0; p < 4; p++) {
            uint32_t da = smem_u32(Asp + (lrow + p * 32) * SPAD + lk);
            asm volatile("cp.async.cg.shared.global [%0], [%1], 16;\n"
                         :: "r"(da), "l"(ag + (size_t)p * 32 * K));
            uint32_t db = smem_u32(Bsp + (lrow + p * 32) * SPAD + lk);
            asm volatile("cp.async.cg.shared.global [%0], [%1], 16;\n"
                         :: "r"(db), "l"(bg + (size_t)p * 32 * K));
        }
        asm volatile("cp.async.commit_group;\n");
    };

    auto compute = [&](int buf) {
        uint16_t* Asp = AsB + buf * 128 * SPAD;
        uint16_t* Bsp = BsB + buf * 128 * SPAD;
        #pragma unroll
        for (int ks = 0; ks < 4; ks++) {
            int kb = ks * 16;
            uint32_t af[4][4];
            #pragma unroll
            for (int im = 0; im < 4; im++) {
                const uint16_t* ap0 = Asp + (warpM + im * 16 + gid) * SPAD + kb + tig * 2;
                const uint16_t* ap1 = ap0 + 8 * SPAD;
                af[im][0] = *(const uint32_t*)(ap0);
                af[im][1] = *(const uint32_t*)(ap1);
                af[im][2] = *(const uint32_t*)(ap0 + 8);
                af[im][3] = *(const uint32_t*)(ap1 + 8);
            }
            uint32_t bf[4][2];
            #pragma unroll
            for (int jn = 0; jn < 4; jn++) {
                const uint16_t* bp = Bsp + (warpN + jn * 8 + gid) * SPAD + kb + tig * 2;
                bf[jn][0] = *(const uint32_t*)(bp);
                bf[jn][1] = *(const uint32_t*)(bp + 8);
            }
            #pragma unroll
            for (int im = 0; im < 4; im++)
                #pragma unroll
                for (int jn = 0; jn < 4; jn++)
                    mma_bf16(acc[im][jn], af[im], bf[jn][0], bf[jn][1]);
        }
    };

    int nt = K / GBK;
    issue(0, 0);
    for (int i = 0; i < nt; i++) {
        if (i + 1 < nt) {
            issue(i + 1, (i + 1) & 1);
            asm volatile("cp.async.wait_group 1;\n");
        } else {
            asm volatile("cp.async.wait_group 0;\n");
        }
        __syncthreads();
        compute(i & 1);
        __syncthreads();
    }

    // Epilogue
    #pragma unroll
    for (int im = 0; im < 4; im++) {
        #pragma unroll
        for (int jn = 0; jn < 4; jn++) {
            int col = n0 + warpN + jn * 8 + tig * 2;
            float b0v = bias[col], b1v = bias[col + 1];
            #pragma unroll
            for (int half = 0; half < 2; half++) {
                int row = m0 + warpM + im * 16 + gid + half * 8;
                float v0 = acc[im][jn][half * 2 + 0] + b0v;
                float v1 = acc[im][jn][half * 2 + 1] + b1v;
                if (EPI == EPI_GELU) {
                    v0 = 0.5f * v0 * (1.0f + erff(v0 * 0.70710678118654752f));
                    v1 = 0.5f * v1 * (1.0f + erff(v1 * 0.70710678118654752f));
                }
                if (EPI == EPI_RES) {
                    float2 rr = *(const float2*)(res + (size_t)row * N + col);
                    float2 o2; o2.x = v0 + rr.x; o2.y = v1 + rr.y;
                    *(float2*)((float*)Cv + (size_t)row * N + col) = o2;
                } else {
                    __nv_bfloat162 pk = __floats2bfloat162_rn(v0, v1);
                    *(uint32_t*)((__nv_bfloat16*)Cv + (size_t)row * N + col) =
                        *(uint32_t*)&pk;
                }
            }
        }
    }
}

// ---------------------------------------------------------------------------
// BF16 tensor-core flash attention (scalar fragment loads, no ldmatrix).
//   One block per (b, h, 128-query tile). 8 warps x 16 q rows, k-tiles of 64.
//   S = QK^T and O += PV via m16n8k16 bf16 MMA. Softmax fp32 in registers.
// Smem (bf16): Qs[128][72], Ks[64][72], Vt[64][72], Ps[128][72]
// ---------------------------------------------------------------------------
#define FTC_SMEM ((128 + 64 + 64 + 128) * SPAD * sizeof(uint16_t))   // 55296 B

__global__ __launch_bounds__(256, 2)
void flash_tc_kernel(const __nv_bfloat16* __restrict__ qkv,
                     __nv_bfloat16* __restrict__ out)
{
    extern __shared__ __align__(16) uint16_t smem_b[];
    uint16_t* Qs = smem_b;                   // [128][SPAD]
    uint16_t* Ks = Qs + 128 * SPAD;          // [64][SPAD]
    uint16_t* Vt = Ks + 64 * SPAD;           // [64][SPAD]
    uint16_t* Ps = Vt + 64 * SPAD;           // [128][SPAD]

    int QT = gridDim.x - 1 - blockIdx.x;
    int h  = blockIdx.y;
    int b  = blockIdx.z;
    int t  = threadIdx.x;
    int lane = t & 31;
    int wid  = t >> 5;
    int gid  = lane >> 2;
    int tig  = lane & 3;
    int warpRow = wid * 16;

    const __nv_bfloat16* base = qkv + (size_t)b * SEQ * QKV_DIM;

    // ---- load Q tile (128 x 64), scale by 0.125 (exact in bf16) ----
    {
        int r  = t >> 1;                    // 0..127
        int d0 = (t & 1) * 32;
        const __nv_bfloat16* qrow = base + (size_t)(QT * 128 + r) * QKV_DIM + h * HDIM + d0;
        __nv_bfloat162 sc = __floats2bfloat162_rn(0.125f, 0.125f);
        uint16_t* dst = Qs + r * SPAD + d0;
        #pragma unroll
        for (int u = 0; u < 4; u++) {
            uint4 raw = ((const uint4*)qrow)[u];
            __nv_bfloat162* pr = (__nv_bfloat162*)&raw;
            #pragma unroll
            for (int e = 0; e < 4; e++) pr[e] = __hmul2(pr[e], sc);
            ((uint4*)dst)[u] = raw;
        }
    }

    float m0 = -1e30f, m1 = -1e30f, l0 = 0.0f, l1 = 0.0f;
    float oacc[8][4];
    #pragma unroll
    for (int dn = 0; dn < 8; dn++)
        #pragma unroll
        for (int r = 0; r < 4; r++) oacc[dn][r] = 0.0f;

    int q0 = QT * 128 + warpRow + gid;
    int ktmax = QT * 2 + 1;

    for (int kt = 0; kt <= ktmax; kt++) {
        __syncthreads();
        // ---- load K tile (64x64 key-major) and V tile (transposed) ----
        {
            int r  = t >> 2;                // 0..63
            int c0 = (t & 3) * 16;
            const __nv_bfloat16* krow = base + (size_t)(kt * 64 + r) * QKV_DIM + DIM + h * HDIM + c0;
            uint16_t* kdst = Ks + r * SPAD + c0;
            ((uint4*)kdst)[0] = ((const uint4*)krow)[0];
            ((uint4*)kdst)[1] = ((const uint4*)krow)[1];

            int j  = t & 63;
            int d0 = (t >> 6) * 16;
            const __nv_bfloat16* vrow = base + (size_t)(kt * 64 + j) * QKV_DIM + 2 * DIM + h * HDIM + d0;
            #pragma unroll
            for (int u = 0; u < 2; u++) {
                uint4 raw = ((const uint4*)vrow)[u];
                uint16_t* rw = (uint16_t*)&raw;
                #pragma unroll
                for (int e = 0; e < 8; e++)
                    Vt[(d0 + u * 8 + e) * SPAD + j] = rw[e];
            }
        }
        __syncthreads();

        // ---- S = Q K^T : warp computes 16 x 64 ----
        float sacc[8][4];
        #pragma unroll
        for (int jn = 0; jn < 8; jn++)
            #pragma unroll
            for (int r = 0; r < 4; r++) sacc[jn][r] = 0.0f;

        #pragma unroll
        for (int ks = 0; ks < 4; ks++) {
            int kb = ks * 16;
            uint32_t af[4];
            {
                const uint16_t* ap0 = Qs + (warpRow + gid) * SPAD + kb + tig * 2;
                const uint16_t* ap1 = ap0 + 8 * SPAD;
                af[0] = *(const uint32_t*)(ap0);
                af[1] = *(const uint32_t*)(ap1);
                af[2] = *(const uint32_t*)(ap0 + 8);
                af[3] = *(const uint32_t*)(ap1 + 8);
            }
            #pragma unroll
            for (int jn = 0; jn < 8; jn++) {
                const uint16_t* bp = Ks + (jn * 8 + gid) * SPAD + kb + tig * 2;
                mma_bf16(sacc[jn], af, *(const uint32_t*)(bp),
                                       *(const uint32_t*)(bp + 8));
            }
        }

        // ---- causal mask ----
        if (kt * 64 + 63 > QT * 128 + warpRow) {
            #pragma unroll
            for (int jn = 0; jn < 8; jn++) {
                int jg = kt * 64 + jn * 8 + tig * 2;
                if (jg     > q0    ) sacc[jn][0] = -1e30f;
                if (jg + 1 > q0    ) sacc[jn][1] = -1e30f;
                if (jg     > q0 + 8) sacc[jn][2] = -1e30f;
                if (jg + 1 > q0 + 8) sacc[jn][3] = -1e30f;
            }
        }

        // ---- online softmax ----
        float rm0 = -1e30f, rm1 = -1e30f;
        #pragma unroll
        for (int jn = 0; jn < 8; jn++) {
            rm0 = fmaxf(rm0, fmaxf(sacc[jn][0], sacc[jn][1]));
            rm1 = fmaxf(rm1, fmaxf(sacc[jn][2], sacc[jn][3]));
        }
        rm0 = fmaxf(rm0, __shfl_xor_sync(0xffffffffu, rm0, 1));
        rm0 = fmaxf(rm0, __shfl_xor_sync(0xffffffffu, rm0, 2));
        rm1 = fmaxf(rm1, __shfl_xor_sync(0xffffffffu, rm1, 1));
        rm1 = fmaxf(rm1, __shfl_xor_sync(0xffffffffu, rm1, 2));

        float mn0 = fmaxf(m0, rm0);
        float mn1 = fmaxf(m1, rm1);
        float a0 = __expf(m0 - mn0);
        float a1 = __expf(m1 - mn1);

        float rs0 = 0.0f, rs1 = 0.0f;
        #pragma unroll
        for (int jn = 0; jn < 8; jn++) {
            float p0 = __expf(sacc[jn][0] - mn0);
            float p1 = __expf(sacc[jn][1] - mn0);
            float p2 = __expf(sacc[jn][2] - mn1);
            float p3 = __expf(sacc[jn][3] - mn1);
            rs0 += p0 + p1;
            rs1 += p2 + p3;
            int col = jn * 8 + tig * 2;
            __nv_bfloat162 w0 = __floats2bfloat162_rn(p0, p1);
            __nv_bfloat162 w1 = __floats2bfloat162_rn(p2, p3);
            *(uint32_t*)(Ps + (warpRow + gid    ) * SPAD + col) = *(uint32_t*)&w0;
            *(uint32_t*)(Ps + (warpRow + gid + 8) * SPAD + col) = *(uint32_t*)&w1;
        }
        rs0 += __shfl_xor_sync(0xffffffffu, rs0, 1);
        rs0 += __shfl_xor_sync(0xffffffffu, rs0, 2);
        rs1 += __shfl_xor_sync(0xffffffffu, rs1, 1);
        rs1 += __shfl_xor_sync(0xffffffffu, rs1, 2);

        l0 = l0 * a0 + rs0; m0 = mn0;
        l1 = l1 * a1 + rs1; m1 = mn1;
        #pragma unroll
        for (int dn = 0; dn < 8; dn++) {
            oacc[dn][0] *= a0; oacc[dn][1] *= a0;
            oacc[dn][2] *= a1; oacc[dn][3] *= a1;
        }
        __syncwarp();

        // ---- O += P V : warp computes 16 x 64 ----
        #pragma unroll
        for (int ks = 0; ks < 4; ks++) {
            int kb = ks * 16;
            uint32_t af[4];
            {
                const uint16_t* ap0 = Ps + (warpRow + gid) * SPAD + kb + tig * 2;
                const uint16_t* ap1 = ap0 + 8 * SPAD;
                af[0] = *(const uint32_t*)(ap0);
                af[1] = *(const uint32_t*)(ap1);
                af[2] = *(const uint32_t*)(ap0 + 8);
                af[3] = *(const uint32_t*)(ap1 + 8);
            }
            #pragma unroll
            for (int dn = 0; dn < 8; dn++) {
                const uint16_t* bp = Vt + (dn * 8 + gid) * SPAD + kb + tig * 2;
                mma_bf16(oacc[dn], af, *(const uint32_t*)(bp),
                                       *(const uint32_t*)(bp + 8));
            }
        }
        __syncwarp();
    }

    // ---- epilogue: normalize, store bf16 (feeds proj A operand) ----
    float inv0 = 1.0f / l0;
    float inv1 = 1.0f / l1;
    __nv_bfloat16* orow0 = out + ((size_t)(b * SEQ) + q0    ) * DIM + h * HDIM;
    __nv_bfloat16* orow1 = out + ((size_t)(b * SEQ) + q0 + 8) * DIM + h * HDIM;
    #pragma unroll
    for (int dn = 0; dn < 8; dn++) {
        int col = dn * 8 + tig * 2;
        __nv_bfloat162 w0 = __floats2bfloat162_rn(oacc[dn][0] * inv0, oacc[dn][1] * inv0);
        __nv_bfloat162 w1 = __floats2bfloat162_rn(oacc[dn][2] * inv1, oacc[dn][3] * inv1);
        *(uint32_t*)(orow0 + col) = *(uint32_t*)&w0;
        *(uint32_t*)(orow1 + col) = *(uint32_t*)&w1;
    }
}

// ---------------------------------------------------------------------------
// Launcher
// ---------------------------------------------------------------------------
extern "C" void kernel_launch(void* const* d_in, const int* in_sizes, int n_in,
                              void* d_out, int out_size)
{
    const float* x      = (const float*)d_in[0];
    const float* qkv_w  = (const float*)d_in[1];
    const float* qkv_b  = (const float*)d_in[2];
    const float* proj_w = (const float*)d_in[3];
    const float* proj_b = (const float*)d_in[4];
    const float* ff1_w  = (const float*)d_in[5];
    const float* ff1_b  = (const float*)d_in[6];
    const float* ff2_w  = (const float*)d_in[7];
    const float* ff2_b  = (const float*)d_in[8];
    const float* ln1_g  = (const float*)d_in[9];
    const float* ln1_b  = (const float*)d_in[10];
    const float* ln2_g  = (const float*)d_in[11];
    const float* ln2_b  = (const float*)d_in[12];
    float* out = (float*)d_out;

    __nv_bfloat16 *xn, *qkv, *att, *hbuf, *wq, *wp, *w1, *w2;
    float *x1;
    cudaGetSymbolAddress((void**)&xn,   g_xn);
    cudaGetSymbolAddress((void**)&qkv,  g_qkv);
    cudaGetSymbolAddress((void**)&att,  g_att);
    cudaGetSymbolAddress((void**)&x1,   g_x1);
    cudaGetSymbolAddress((void**)&hbuf, g_h);
    cudaGetSymbolAddress((void**)&wq,   g_wq);
    cudaGetSymbolAddress((void**)&wp,   g_wp);
    cudaGetSymbolAddress((void**)&w1,   g_w1);
    cudaGetSymbolAddress((void**)&w2,   g_w2);

    cudaFuncSetAttribute(flash_tc_kernel,
                         cudaFuncAttributeMaxDynamicSharedMemorySize, FTC_SMEM);
    cudaFuncSetAttribute(gemm_bf16_kernel<EPI_BIAS>,
                         cudaFuncAttributeMaxDynamicSharedMemorySize, GEMM_SMEM);
    cudaFuncSetAttribute(gemm_bf16_kernel<EPI_GELU>,
                         cudaFuncAttributeMaxDynamicSharedMemorySize, GEMM_SMEM);
    cudaFuncSetAttribute(gemm_bf16_kernel<EPI_RES>,
                         cudaFuncAttributeMaxDynamicSharedMemorySize, GEMM_SMEM);

    // 0. Convert weights to bf16
    cvt_bf16_kernel<<<(QKV_DIM * DIM / 4 + 255) / 256, 256>>>(qkv_w, wq, QKV_DIM * DIM);
    cvt_bf16_kernel<<<(DIM * DIM / 4 + 255) / 256, 256>>>(proj_w, wp, DIM * DIM);
    cvt_bf16_kernel<<<(HIDDEN * DIM / 4 + 255) / 256, 256>>>(ff1_w, w1, HIDDEN * DIM);
    cvt_bf16_kernel<<<(DIM * HIDDEN / 4 + 255) / 256, 256>>>(ff2_w, w2, DIM * HIDDEN);

    // 1. LN1 -> bf16
    ln_kernel<<<TOKENS, 256>>>(x, ln1_g, ln1_b, xn);

    // 2. QKV projection -> bf16
    {
        dim3 grid(QKV_DIM / 128, TOKENS / 128);
        gemm_bf16_kernel<EPI_BIAS><<<grid, 256, GEMM_SMEM>>>(xn, wq, qkv_b, nullptr, qkv,
                                                             TOKENS, QKV_DIM, DIM);
    }

    // 3. Flash attention -> bf16
    {
        dim3 grid(SEQ / 128, NHEAD, BATCH);
        flash_tc_kernel<<<grid, 256, FTC_SMEM>>>(qkv, att);
    }

    // 4. proj + residual -> fp32 x1
    {
        dim3 grid(DIM / 128, TOKENS / 128);
        gemm_bf16_kernel<EPI_RES><<<grid, 256, GEMM_SMEM>>>(att, wp, proj_b, x, x1,
                                                            TOKENS, DIM, DIM);
    }

    // 5. LN2 -> bf16
    ln_kernel<<<TOKENS, 256>>>(x1, ln2_g, ln2_b, xn);

    // 6. FF1 + GELU -> bf16
    {
        dim3 grid(HIDDEN / 128, TOKENS / 128);
        gemm_bf16_kernel<EPI_GELU><<<grid, 256, GEMM_SMEM>>>(xn, w1, ff1_b, nullptr, hbuf,
                                                             TOKENS, HIDDEN, DIM);
    }

    // 7. FF2 + residual -> fp32 d_out
    {
        dim3 grid(DIM / 128, TOKENS / 128);
        gemm_bf16_kernel<EPI_RES><<<grid, 256, GEMM_SMEM>>>(hbuf, w2, ff2_b, x1, out,
                                                            TOKENS, DIM, HIDDEN);
    }
}